// round 8
// baseline (speedup 1.0000x reference)
#include <cuda_runtime.h>
#include <cuda_bf16.h>
#include <math.h>
#include <stdint.h>

#define Bz 512
#define Sz 100
#define Ez 256
#define Hz 256
#define G4 1024
#define C_EXPLORE 10.0f
#define PARTITIONABLE 1

typedef unsigned long long u64;

// ---------------- packed f32x2 helpers (sm_100+) ----------------
__device__ __forceinline__ u64 pk2(float lo, float hi) {
    u64 d; asm("mov.b64 %0, {%1, %2};" : "=l"(d) : "f"(lo), "f"(hi)); return d;
}
__device__ __forceinline__ void upk2(u64 v, float& lo, float& hi) {
    asm("mov.b64 {%0, %1}, %2;" : "=f"(lo), "=f"(hi) : "l"(v));
}
__device__ __forceinline__ u64 fma2(u64 a, u64 b, u64 c) {
    u64 d; asm("fma.rn.f32x2 %0, %1, %2, %3;" : "=l"(d) : "l"(a), "l"(b), "l"(c)); return d;
}

// ---------------- fast exact-enough tanh: Eigen/XLA rational + rcp.approx NR ----------------
__device__ __forceinline__ float xtanh(float x) {
    const float c = 7.90531110763549805f;
    float cx = fminf(fmaxf(x, -c), c);
    float r = cx * cx;
    float p = -2.76076847742355e-16f;
    p = fmaf(p, r, 2.00018790482477e-13f);
    p = fmaf(p, r, -8.60467152213735e-11f);
    p = fmaf(p, r, 5.12229709037114e-08f);
    p = fmaf(p, r, 1.48572235717979e-05f);
    p = fmaf(p, r, 6.37261928875436e-04f);
    p = fmaf(p, r, 4.89352455891786e-03f);
    float num = cx * p;
    float q = 1.19825839466702e-06f;
    q = fmaf(q, r, 1.18534705686654e-04f);
    q = fmaf(q, r, 2.26843463243900e-03f);
    q = fmaf(q, r, 4.89352518554385e-03f);
    float ri;
    asm("rcp.approx.f32 %0, %1;" : "=f"(ri) : "f"(q));
    ri = ri * fmaf(-q, ri, 2.0f);   // Newton: error -> ~2^-26
    return num * ri;
}
__device__ __forceinline__ float sigf(float x) {
    return 0.5f + 0.5f * xtanh(0.5f * x);
}

// ---------------- device state ----------------
__device__ float g_h0[Bz * Hz];
__device__ float g_h1[Bz * Hz];
__device__ float g_c[Bz * Hz];
__device__ float g_enc[(size_t)Bz * Sz * Hz];
__device__ float g_refg[(size_t)Bz * Sz * Hz];
__device__ float g_refp[(size_t)Bz * Sz * Hz];
__device__ float g_Penc[2 * G4];
__device__ float g_Pdec[2 * G4];
__device__ float g_startproj[G4];
__device__ int g_idx[Bz];
__device__ unsigned char g_mask[Bz * Sz];

// ---------------- threefry2x32 ----------------
__device__ __forceinline__ unsigned rotl32(unsigned v, int r) {
    return (v << r) | (v >> (32 - r));
}
__device__ __forceinline__ void tf2x32(unsigned k0, unsigned k1,
                                       unsigned x0, unsigned x1,
                                       unsigned& o0, unsigned& o1) {
    unsigned ks2 = 0x1BD11BDAu ^ k0 ^ k1;
    x0 += k0; x1 += k1;
#define TF_G(a,b,c,d) \
    x0 += x1; x1 = rotl32(x1,a); x1 ^= x0; \
    x0 += x1; x1 = rotl32(x1,b); x1 ^= x0; \
    x0 += x1; x1 = rotl32(x1,c); x1 ^= x0; \
    x0 += x1; x1 = rotl32(x1,d); x1 ^= x0;
    TF_G(13,15,26,6);  x0 += k1;  x1 += ks2 + 1u;
    TF_G(17,29,16,24); x0 += ks2; x1 += k0 + 2u;
    TF_G(13,15,26,6);  x0 += k0;  x1 += k1 + 3u;
    TF_G(17,29,16,24); x0 += k1;  x1 += ks2 + 4u;
    TF_G(13,15,26,6);  x0 += ks2; x1 += k0 + 5u;
#undef TF_G
    o0 = x0; o1 = x1;
}

// ---------------- setup ----------------
__global__ void k_init() {
    int i = blockIdx.x * blockDim.x + threadIdx.x;
    if (i < Bz * Hz) { g_h0[i] = 0.f; g_c[i] = 0.f; }
    if (i < Bz * Sz) g_mask[i] = 0;
    if (i < Bz) g_idx[i] = 0;
}

__global__ void k_prep(const float* __restrict__ emb,
                       const float* __restrict__ eWih,
                       const float* __restrict__ dWih,
                       const float* __restrict__ start) {
    int j = blockIdx.x * 256 + threadIdx.x;
    if (j >= G4) return;
    float pe0 = 0.f, pe1 = 0.f, pd0 = 0.f, pd1 = 0.f, sp = 0.f;
    for (int e = 0; e < Ez; e++) {
        float we = eWih[j * Ez + e], wd = dWih[j * Ez + e];
        pe0 = fmaf(emb[e], we, pe0);
        pe1 = fmaf(emb[Ez + e], we, pe1);
        pd0 = fmaf(emb[e], wd, pd0);
        pd1 = fmaf(emb[Ez + e], wd, pd1);
        sp  = fmaf(start[e], wd, sp);
    }
    g_Penc[j] = pe0; g_Penc[G4 + j] = pe1;
    g_Pdec[j] = pd0; g_Pdec[G4 + j] = pd1;
    g_startproj[j] = sp;
}

// ---------------- fused gates GEMM + LSTM cell, f32x2 packed FMA ----------------
// block = 32 b-rows x 32 j-cols x 4 gates; W in smem as gate-pair float2
__global__ void __launch_bounds__(256) k_lstm_step(const float* __restrict__ rh,
                                                   float* __restrict__ wh,
                                                   const float* __restrict__ W,
                                                   const float* __restrict__ bih,
                                                   const float* __restrict__ bhh,
                                                   const float* __restrict__ inp,
                                                   int t, int is_dec) {
    __shared__ float sA[2][32 * 36];
    __shared__ float2 sW01[2][32 * 33];
    __shared__ float2 sW23[2][32 * 33];
    const int tid = threadIdx.x, bid = blockIdx.x;
    const int tx = tid & 31, ty = tid >> 5;
    const int bm = (bid >> 3) * 32, jn = (bid & 7) * 32;
    const int j = jn + tx;
    const int lrow = tid >> 3;          // 0..31
    const int lk = (tid & 7) << 2;      // 0,4,..,28

    const float* Ab  = rh + (size_t)(bm + lrow) * Hz + lk;
    const float* Wb0 = W + (size_t)(jn + lrow) * Hz + lk;
    const float* Wb1 = Wb0 + (size_t)256 * Hz;
    const float* Wb2 = Wb0 + (size_t)512 * Hz;
    const float* Wb3 = Wb0 + (size_t)768 * Hz;

    float4 pa  = *(const float4*)Ab;
    float4 pw0 = *(const float4*)Wb0;
    float4 pw1 = *(const float4*)Wb1;
    float4 pw2 = *(const float4*)Wb2;
    float4 pw3 = *(const float4*)Wb3;

    u64 acc2[4][2];   // [row r][gate pair]: {g0,g1},{g2,g3}
#pragma unroll
    for (int r = 0; r < 4; r++) { acc2[r][0] = pk2(0.f, 0.f); acc2[r][1] = acc2[r][0]; }

    for (int k0 = 0; k0 < Hz; k0 += 32) {
        const int buf = (k0 >> 5) & 1;
        float* a_s = sA[buf];
        float2* w01 = sW01[buf];
        float2* w23 = sW23[buf];
        a_s[(lk + 0) * 36 + lrow] = pa.x;
        a_s[(lk + 1) * 36 + lrow] = pa.y;
        a_s[(lk + 2) * 36 + lrow] = pa.z;
        a_s[(lk + 3) * 36 + lrow] = pa.w;
        {
            const float* p0 = (const float*)&pw0;
            const float* p1 = (const float*)&pw1;
            const float* p2 = (const float*)&pw2;
            const float* p3 = (const float*)&pw3;
#pragma unroll
            for (int i = 0; i < 4; i++) {
                w01[(lk + i) * 33 + lrow] = make_float2(p0[i], p1[i]);
                w23[(lk + i) * 33 + lrow] = make_float2(p2[i], p3[i]);
            }
        }
        __syncthreads();
        if (k0 + 32 < Hz) {
            pa  = *(const float4*)(Ab + k0 + 32);
            pw0 = *(const float4*)(Wb0 + k0 + 32);
            pw1 = *(const float4*)(Wb1 + k0 + 32);
            pw2 = *(const float4*)(Wb2 + k0 + 32);
            pw3 = *(const float4*)(Wb3 + k0 + 32);
        }
#pragma unroll 8
        for (int k = 0; k < 32; k++) {
            float4 a4 = *(const float4*)&a_s[k * 36 + (ty << 2)];  // warp broadcast
            float2 wv01 = w01[k * 33 + tx];
            float2 wv23 = w23[k * 33 + tx];
            u64 wp01 = pk2(wv01.x, wv01.y);
            u64 wp23 = pk2(wv23.x, wv23.y);
            u64 ax = pk2(a4.x, a4.x);
            u64 ay = pk2(a4.y, a4.y);
            u64 az = pk2(a4.z, a4.z);
            u64 aw = pk2(a4.w, a4.w);
            acc2[0][0] = fma2(wp01, ax, acc2[0][0]);
            acc2[0][1] = fma2(wp23, ax, acc2[0][1]);
            acc2[1][0] = fma2(wp01, ay, acc2[1][0]);
            acc2[1][1] = fma2(wp23, ay, acc2[1][1]);
            acc2[2][0] = fma2(wp01, az, acc2[2][0]);
            acc2[2][1] = fma2(wp23, az, acc2[2][1]);
            acc2[3][0] = fma2(wp01, aw, acc2[3][0]);
            acc2[3][1] = fma2(wp23, aw, acc2[3][1]);
        }
        __syncthreads();
    }

    const float* P = is_dec ? g_Pdec : g_Penc;
    float xb[4], pb0[4], pb1[4];
#pragma unroll
    for (int g = 0; g < 4; g++) {
        pb0[g] = P[(g << 8) + j];
        pb1[g] = P[G4 + (g << 8) + j];
        xb[g]  = bih[(g << 8) + j] + bhh[(g << 8) + j];
    }
#pragma unroll
    for (int r = 0; r < 4; r++) {
        int b = bm + (ty << 2) + r;
        float a0, a1, a2, a3;
        upk2(acc2[r][0], a0, a1);
        upk2(acc2[r][1], a2, a3);
        float xg[4];
        if (is_dec && t == 0) {
#pragma unroll
            for (int g = 0; g < 4; g++) xg[g] = g_startproj[(g << 8) + j];
        } else {
            int s = is_dec ? g_idx[b] : t;
            float c0 = inp[(b * 2) * Sz + s];
            float c1 = inp[(b * 2 + 1) * Sz + s];
#pragma unroll
            for (int g = 0; g < 4; g++) xg[g] = fmaf(c0, pb0[g], c1 * pb1[g]);
        }
        float gi = a0 + xg[0] + xb[0];
        float gf = a1 + xg[1] + xb[1];
        float gc = a2 + xg[2] + xb[2];
        float go = a3 + xg[3] + xb[3];
        float cc = sigf(gf) * g_c[b * Hz + j] + sigf(gi) * xtanh(gc);
        g_c[b * Hz + j] = cc;
        float hh = sigf(go) * xtanh(cc);
        wh[b * Hz + j] = hh;
        if (!is_dec) g_enc[(size_t)(b * Sz + t) * Hz + j] = hh;
    }
}

// ---------------- ref projections (z=0: glimpse, z=1: pointer) ----------------
__global__ void __launch_bounds__(256) k_ref(const float* __restrict__ gWr,
                                             const float* __restrict__ gbr,
                                             const float* __restrict__ pWr,
                                             const float* __restrict__ pbr) {
    __shared__ float As[16][64];
    __shared__ float Ws[16][64];
    const float* A = g_enc;
    const float* W = blockIdx.z ? pWr : gWr;
    const float* bias = blockIdx.z ? pbr : gbr;
    float* C = blockIdx.z ? g_refp : g_refg;
    const int K = Hz, N = Hz;
    const int bm = blockIdx.y * 64;
    const int bn = blockIdx.x * 64;
    const int t = threadIdx.x;
    const int tx = t & 15, ty = t >> 4;
    const int lr = t >> 2, lc = (t & 3) << 2;
    float acc[4][4];
#pragma unroll
    for (int i = 0; i < 4; i++)
#pragma unroll
        for (int jj = 0; jj < 4; jj++) acc[i][jj] = 0.f;
    const float* Ab = A + (size_t)(bm + lr) * K + lc;
    const float* Wb = W + (size_t)(bn + lr) * K + lc;
    for (int k0 = 0; k0 < K; k0 += 16) {
        float4 av = *(const float4*)(Ab + k0);
        float4 wv = *(const float4*)(Wb + k0);
        As[lc + 0][lr] = av.x; As[lc + 1][lr] = av.y;
        As[lc + 2][lr] = av.z; As[lc + 3][lr] = av.w;
        Ws[lc + 0][lr] = wv.x; Ws[lc + 1][lr] = wv.y;
        Ws[lc + 2][lr] = wv.z; Ws[lc + 3][lr] = wv.w;
        __syncthreads();
#pragma unroll
        for (int k = 0; k < 16; k++) {
            float4 a4 = *(const float4*)&As[k][ty << 2];
            float4 w4 = *(const float4*)&Ws[k][tx << 2];
            float am[4] = {a4.x, a4.y, a4.z, a4.w};
            float wn[4] = {w4.x, w4.y, w4.z, w4.w};
#pragma unroll
            for (int i = 0; i < 4; i++)
#pragma unroll
                for (int jj = 0; jj < 4; jj++)
                    acc[i][jj] = fmaf(am[i], wn[jj], acc[i][jj]);
        }
        __syncthreads();
    }
#pragma unroll
    for (int i = 0; i < 4; i++) {
        int m = bm + (ty << 2) + i;
#pragma unroll
        for (int jj = 0; jj < 4; jj++) {
            int n = bn + (tx << 2) + jj;
            C[(size_t)m * N + n] = acc[i][jj] + bias[n];
        }
    }
}

// ---------------- fused decoder attention + sample: TWO b per block, 512 thr ----------------
__global__ void __launch_bounds__(512) k_dec_attn(const float* __restrict__ h,
                                                  const float* __restrict__ gWq,
                                                  const float* __restrict__ gbq,
                                                  const float* __restrict__ gV,
                                                  const float* __restrict__ pWq,
                                                  const float* __restrict__ pbq,
                                                  const float* __restrict__ pV,
                                                  float* __restrict__ out_probs,
                                                  float* __restrict__ out_idx,
                                                  int t) {
    __shared__ __align__(16) float s_h[2][Hz];
    __shared__ __align__(16) float s_qq[2][Hz];
    __shared__ __align__(16) float s_q[2][Hz];
    __shared__ __align__(16) float s_Vg[Hz];
    __shared__ __align__(16) float s_Vp[Hz];
    __shared__ float s_lg[2][128];
    __shared__ float s_w[2][128];
    __shared__ float s_red[2][256];
    __shared__ int s_ridx[2][256];
    __shared__ unsigned char s_m[2][104];

    const int tid = threadIdx.x;
    const int half = tid >> 8;
    const int ht = tid & 255;
    const int b = (blockIdx.x << 1) + half;
    const int wd = tid >> 5;
    const int hf = wd >> 3;
    const int wl = wd & 7;
    const int ln = tid & 31;
    const int bw = (blockIdx.x << 1) + hf;

    if (t > 0 && ht == 0) g_mask[b * Sz + g_idx[b]] = 1;
    __syncthreads();
    if (ht < Sz) s_m[half][ht] = g_mask[b * Sz + ht];
    s_h[half][ht] = h[b * Hz + ht];
    if (tid < Hz) s_Vg[tid] = gV[tid];
    else if (tid < 2 * Hz) s_Vp[tid - Hz] = pV[tid - Hz];
    __syncthreads();

    // qq = h @ gWq^T + gbq for both b's (W read once)
    if (tid < Hz) {
        float a0 = 0.f, a1 = 0.f;
        const float* wr = gWq + (size_t)tid * Hz;
#pragma unroll 8
        for (int k0 = 0; k0 < Hz; k0 += 4) {
            float4 wv = *(const float4*)&wr[k0];
            float4 h0 = *(const float4*)&s_h[0][k0];
            float4 h1 = *(const float4*)&s_h[1][k0];
            a0 = fmaf(h0.x, wv.x, a0); a1 = fmaf(h1.x, wv.x, a1);
            a0 = fmaf(h0.y, wv.y, a0); a1 = fmaf(h1.y, wv.y, a1);
            a0 = fmaf(h0.z, wv.z, a0); a1 = fmaf(h1.z, wv.z, a1);
            a0 = fmaf(h0.w, wv.w, a0); a1 = fmaf(h1.w, wv.w, a1);
        }
        float bq = gbq[tid];
        s_qq[0][tid] = a0 + bq;
        s_qq[1][tid] = a1 + bq;
    }
    __syncthreads();
    // glimpse logits
    for (int s = wl; s < Sz; s += 8) {
        float a0 = 0.f, a1 = 0.f;
        if (!s_m[hf][s]) {
            const float4* rg4 = (const float4*)(g_refg + ((size_t)bw * Sz + s) * Hz);
#pragma unroll
            for (int i = 0; i < 2; i++) {
                int c = i * 32 + ln;
                float4 rv = rg4[c];
                float4 qv = *(const float4*)&s_qq[hf][c << 2];
                float4 vv = *(const float4*)&s_Vg[c << 2];
                a0 = fmaf(vv.x, xtanh(qv.x + rv.x), a0);
                a1 = fmaf(vv.y, xtanh(qv.y + rv.y), a1);
                a0 = fmaf(vv.z, xtanh(qv.z + rv.z), a0);
                a1 = fmaf(vv.w, xtanh(qv.w + rv.w), a1);
            }
        }
        float a = a0 + a1;
#pragma unroll
        for (int o = 16; o; o >>= 1) a += __shfl_xor_sync(0xffffffffu, a, o);
        if (!ln) s_lg[hf][s] = s_m[hf][s] ? -INFINITY : a;
    }
    __syncthreads();
    // softmax -> s_w
    {
        float v = (ht < Sz) ? s_lg[half][ht] : -INFINITY;
        s_red[half][ht] = v; __syncthreads();
#pragma unroll
        for (int o = 128; o; o >>= 1) { if (ht < o) s_red[half][ht] = fmaxf(s_red[half][ht], s_red[half][ht + o]); __syncthreads(); }
        float m = s_red[half][0]; __syncthreads();
        float e = (ht < Sz) ? expf(v - m) : 0.f;
        s_red[half][ht] = e; __syncthreads();
#pragma unroll
        for (int o = 128; o; o >>= 1) { if (ht < o) s_red[half][ht] += s_red[half][ht + o]; __syncthreads(); }
        float sm = s_red[half][0]; __syncthreads();
        if (ht < 128) s_w[half][ht] = (ht < Sz) ? e / sm : 0.f;
    }
    __syncthreads();
    // q = sum_s w[s] * enc[b,s,:]
    {
        float a0 = 0.f, a1 = 0.f;
        const float* eb = g_enc + (size_t)b * Sz * Hz + ht;
        for (int s = 0; s < Sz; s += 2) {
            a0 = fmaf(s_w[half][s], eb[(size_t)s * Hz], a0);
            a1 = fmaf(s_w[half][s + 1], eb[(size_t)(s + 1) * Hz], a1);
        }
        s_q[half][ht] = a0 + a1;
    }
    __syncthreads();
    // qq2 = q @ pWq^T + pbq
    if (tid < Hz) {
        float a0 = 0.f, a1 = 0.f;
        const float* wr = pWq + (size_t)tid * Hz;
#pragma unroll 8
        for (int k0 = 0; k0 < Hz; k0 += 4) {
            float4 wv = *(const float4*)&wr[k0];
            float4 q0 = *(const float4*)&s_q[0][k0];
            float4 q1 = *(const float4*)&s_q[1][k0];
            a0 = fmaf(q0.x, wv.x, a0); a1 = fmaf(q1.x, wv.x, a1);
            a0 = fmaf(q0.y, wv.y, a0); a1 = fmaf(q1.y, wv.y, a1);
            a0 = fmaf(q0.z, wv.z, a0); a1 = fmaf(q1.z, wv.z, a1);
            a0 = fmaf(q0.w, wv.w, a0); a1 = fmaf(q1.w, wv.w, a1);
        }
        float bq = pbq[tid];
        s_qq[0][tid] = a0 + bq;
        s_qq[1][tid] = a1 + bq;
    }
    __syncthreads();
    // pointer logits
    for (int s = wl; s < Sz; s += 8) {
        float a0 = 0.f, a1 = 0.f;
        if (!s_m[hf][s]) {
            const float4* rp4 = (const float4*)(g_refp + ((size_t)bw * Sz + s) * Hz);
#pragma unroll
            for (int i = 0; i < 2; i++) {
                int c = i * 32 + ln;
                float4 rv = rp4[c];
                float4 qv = *(const float4*)&s_qq[hf][c << 2];
                float4 vv = *(const float4*)&s_Vp[c << 2];
                a0 = fmaf(vv.x, xtanh(qv.x + rv.x), a0);
                a1 = fmaf(vv.y, xtanh(qv.y + rv.y), a1);
                a0 = fmaf(vv.z, xtanh(qv.z + rv.z), a0);
                a1 = fmaf(vv.w, xtanh(qv.w + rv.w), a1);
            }
        }
        float a = a0 + a1;
#pragma unroll
        for (int o = 16; o; o >>= 1) a += __shfl_xor_sync(0xffffffffu, a, o);
        if (!ln) s_lg[hf][s] = s_m[hf][s] ? -INFINITY : C_EXPLORE * xtanh(a);
    }
    __syncthreads();
    // softmax -> probs; gumbel argmax -> idx
    {
        float v = (ht < Sz) ? s_lg[half][ht] : -INFINITY;
        s_red[half][ht] = v; __syncthreads();
#pragma unroll
        for (int o = 128; o; o >>= 1) { if (ht < o) s_red[half][ht] = fmaxf(s_red[half][ht], s_red[half][ht + o]); __syncthreads(); }
        float m = s_red[half][0]; __syncthreads();
        float e = (ht < Sz) ? expf(v - m) : 0.f;
        s_red[half][ht] = e; __syncthreads();
#pragma unroll
        for (int o = 128; o; o >>= 1) { if (ht < o) s_red[half][ht] += s_red[half][ht + o]; __syncthreads(); }
        float sm = s_red[half][0]; __syncthreads();
        if (ht < Sz)
            out_probs[(size_t)b * Sz + ht] = e / sm;
        float pv = -INFINITY;
        if (ht < Sz) {
            unsigned key0, key1;
#if PARTITIONABLE
            tf2x32(0u, 1u, 0u, (unsigned)t, key0, key1);
#else
            {
                unsigned a0, b0;
                unsigned idx0 = 2u * t, idx1 = 2u * t + 1u;
                if (idx0 < Sz) { tf2x32(0u, 1u, idx0, idx0 + Sz, a0, b0); key0 = a0; }
                else           { tf2x32(0u, 1u, idx0 - Sz, idx0, a0, b0); key0 = b0; }
                if (idx1 < Sz) { tf2x32(0u, 1u, idx1, idx1 + Sz, a0, b0); key1 = a0; }
                else           { tf2x32(0u, 1u, idx1 - Sz, idx1, a0, b0); key1 = b0; }
            }
#endif
            unsigned m0 = (unsigned)(b * Sz + ht);
            unsigned ra, rb, bits;
#if PARTITIONABLE
            tf2x32(key0, key1, 0u, m0, ra, rb);
            bits = ra ^ rb;
#else
            const unsigned halfn = (Bz * Sz) / 2;
            if (m0 < halfn) { tf2x32(key0, key1, m0, m0 + halfn, ra, rb); bits = ra; }
            else            { tf2x32(key0, key1, m0 - halfn, m0, ra, rb); bits = rb; }
#endif
            float f = __uint_as_float((bits >> 9) | 0x3f800000u) - 1.0f;
            float u = fmaxf(f, 1.17549435e-38f);
            pv = v - logf(-logf(u));
        }
        s_red[half][ht] = pv; s_ridx[half][ht] = ht; __syncthreads();
#pragma unroll
        for (int o = 128; o; o >>= 1) {
            if (ht < o) {
                float a2 = s_red[half][ht], c2 = s_red[half][ht + o];
                int ia = s_ridx[half][ht], ic = s_ridx[half][ht + o];
                if (c2 > a2 || (c2 == a2 && ic < ia)) { s_red[half][ht] = c2; s_ridx[half][ht] = ic; }
            }
            __syncthreads();
        }
        if (!ht) {
            int id = s_ridx[half][0];
            g_idx[b] = id;
            out_idx[b] = (float)id;
        }
    }
}

// ---------------- host ----------------
template <typename T>
static T* symaddr(const void* sym) {
    void* p = nullptr;
    cudaGetSymbolAddress(&p, sym);
    return (T*)p;
}

extern "C" void kernel_launch(void* const* d_in, const int* in_sizes, int n_in,
                              void* d_out, int out_size) {
    const float* in_inputs = (const float*)d_in[0];
    const float* in_emb    = (const float*)d_in[1];
    const float* in_eWih   = (const float*)d_in[2];
    const float* in_eWhh   = (const float*)d_in[3];
    const float* in_ebih   = (const float*)d_in[4];
    const float* in_ebhh   = (const float*)d_in[5];
    const float* in_dWih   = (const float*)d_in[6];
    const float* in_dWhh   = (const float*)d_in[7];
    const float* in_dbih   = (const float*)d_in[8];
    const float* in_dbhh   = (const float*)d_in[9];
    const float* in_gWq    = (const float*)d_in[10];
    const float* in_gbq    = (const float*)d_in[11];
    const float* in_gWr    = (const float*)d_in[12];
    const float* in_gbr    = (const float*)d_in[13];
    const float* in_gV     = (const float*)d_in[14];
    const float* in_pWq    = (const float*)d_in[15];
    const float* in_pbq    = (const float*)d_in[16];
    const float* in_pWr    = (const float*)d_in[17];
    const float* in_pbr    = (const float*)d_in[18];
    const float* in_pV     = (const float*)d_in[19];
    const float* in_start  = (const float*)d_in[20];
    float* out = (float*)d_out;

    float* p_h0 = symaddr<float>(g_h0);
    float* p_h1 = symaddr<float>(g_h1);

    k_init<<<512, 256>>>();
    k_prep<<<4, 256>>>(in_emb, in_eWih, in_dWih, in_start);

    for (int t = 0; t < Sz; t++) {
        const float* rh = (t & 1) ? p_h1 : p_h0;
        float* wh       = (t & 1) ? p_h0 : p_h1;
        k_lstm_step<<<128, 256>>>(rh, wh, in_eWhh, in_ebih, in_ebhh, in_inputs, t, 0);
    }

    {
        dim3 grid(Hz / 64, (Bz * Sz) / 64, 2);
        k_ref<<<grid, 256>>>(in_gWr, in_gbr, in_pWr, in_pbr);
    }

    float* out_probs = out;
    float* out_idx = out + (size_t)Sz * Bz * Sz;
    for (int t = 0; t < Sz; t++) {
        const float* rh = (t & 1) ? p_h1 : p_h0;
        float* wh       = (t & 1) ? p_h0 : p_h1;
        k_lstm_step<<<128, 256>>>(rh, wh, in_dWhh, in_dbih, in_dbhh, in_inputs, t, 1);
        k_dec_attn<<<Bz / 2, 512>>>(wh, in_gWq, in_gbq, in_gV, in_pWq, in_pbq, in_pV,
                                    out_probs + (size_t)t * Bz * Sz,
                                    out_idx + (size_t)t * Bz, t);
    }
    (void)in_sizes; (void)n_in; (void)out_size;
}

// round 9
// speedup vs baseline: 1.1774x; 1.1774x over previous
#include <cuda_runtime.h>
#include <cuda_bf16.h>
#include <math.h>
#include <stdint.h>

#define Bz 512
#define Sz 100
#define Ez 256
#define Hz 256
#define G4 1024
#define C_EXPLORE 10.0f
#define PARTITIONABLE 1

typedef unsigned long long u64;

// ---------------- packed f32x2 helpers (sm_100+) ----------------
__device__ __forceinline__ u64 pk2(float lo, float hi) {
    u64 d; asm("mov.b64 %0, {%1, %2};" : "=l"(d) : "f"(lo), "f"(hi)); return d;
}
__device__ __forceinline__ void upk2(u64 v, float& lo, float& hi) {
    asm("mov.b64 {%0, %1}, %2;" : "=f"(lo), "=f"(hi) : "l"(v));
}
__device__ __forceinline__ u64 fma2(u64 a, u64 b, u64 c) {
    u64 d; asm("fma.rn.f32x2 %0, %1, %2, %3;" : "=l"(d) : "l"(a), "l"(b), "l"(c)); return d;
}

// ---------------- fast exact-enough tanh (Eigen/XLA rational + rcp NR) ----------------
__device__ __forceinline__ float xtanh(float x) {
    const float c = 7.90531110763549805f;
    float cx = fminf(fmaxf(x, -c), c);
    float r = cx * cx;
    float p = -2.76076847742355e-16f;
    p = fmaf(p, r, 2.00018790482477e-13f);
    p = fmaf(p, r, -8.60467152213735e-11f);
    p = fmaf(p, r, 5.12229709037114e-08f);
    p = fmaf(p, r, 1.48572235717979e-05f);
    p = fmaf(p, r, 6.37261928875436e-04f);
    p = fmaf(p, r, 4.89352455891786e-03f);
    float num = cx * p;
    float q = 1.19825839466702e-06f;
    q = fmaf(q, r, 1.18534705686654e-04f);
    q = fmaf(q, r, 2.26843463243900e-03f);
    q = fmaf(q, r, 4.89352518554385e-03f);
    float ri;
    asm("rcp.approx.f32 %0, %1;" : "=f"(ri) : "f"(q));
    ri = ri * fmaf(-q, ri, 2.0f);
    return num * ri;
}
__device__ __forceinline__ float sigf(float x) {
    return 0.5f + 0.5f * xtanh(0.5f * x);
}

// ---------------- device state ----------------
__device__ float g_h0[Bz * Hz];
__device__ float g_h1[Bz * Hz];
__device__ float g_c[Bz * Hz];
__device__ float g_enc[(size_t)Bz * Sz * Hz];
__device__ float g_refg[(size_t)Bz * Sz * Hz];
__device__ float g_refp[(size_t)Bz * Sz * Hz];
__device__ float g_Penc[2 * G4];
__device__ float g_Pdec[2 * G4];
__device__ float g_startproj[G4];
__device__ int g_idx[Bz];
__device__ unsigned char g_mask[Bz * Sz];

// ---------------- threefry2x32 ----------------
__device__ __forceinline__ unsigned rotl32(unsigned v, int r) {
    return (v << r) | (v >> (32 - r));
}
__device__ __forceinline__ void tf2x32(unsigned k0, unsigned k1,
                                       unsigned x0, unsigned x1,
                                       unsigned& o0, unsigned& o1) {
    unsigned ks2 = 0x1BD11BDAu ^ k0 ^ k1;
    x0 += k0; x1 += k1;
#define TF_G(a,b,c,d) \
    x0 += x1; x1 = rotl32(x1,a); x1 ^= x0; \
    x0 += x1; x1 = rotl32(x1,b); x1 ^= x0; \
    x0 += x1; x1 = rotl32(x1,c); x1 ^= x0; \
    x0 += x1; x1 = rotl32(x1,d); x1 ^= x0;
    TF_G(13,15,26,6);  x0 += k1;  x1 += ks2 + 1u;
    TF_G(17,29,16,24); x0 += ks2; x1 += k0 + 2u;
    TF_G(13,15,26,6);  x0 += k0;  x1 += k1 + 3u;
    TF_G(17,29,16,24); x0 += k1;  x1 += ks2 + 4u;
    TF_G(13,15,26,6);  x0 += ks2; x1 += k0 + 5u;
#undef TF_G
    o0 = x0; o1 = x1;
}

// ---------------- setup ----------------
__global__ void k_init() {
    int i = blockIdx.x * blockDim.x + threadIdx.x;
    if (i < Bz * Hz) { g_h0[i] = 0.f; g_c[i] = 0.f; }
    if (i < Bz * Sz) g_mask[i] = 0;
    if (i < Bz) g_idx[i] = 0;
}

__global__ void k_prep(const float* __restrict__ emb,
                       const float* __restrict__ eWih,
                       const float* __restrict__ dWih,
                       const float* __restrict__ start) {
    int j = blockIdx.x * 256 + threadIdx.x;
    if (j >= G4) return;
    float pe0 = 0.f, pe1 = 0.f, pd0 = 0.f, pd1 = 0.f, sp = 0.f;
    for (int e = 0; e < Ez; e++) {
        float we = eWih[j * Ez + e], wd = dWih[j * Ez + e];
        pe0 = fmaf(emb[e], we, pe0);
        pe1 = fmaf(emb[Ez + e], we, pe1);
        pd0 = fmaf(emb[e], wd, pd0);
        pd1 = fmaf(emb[Ez + e], wd, pd1);
        sp  = fmaf(start[e], wd, sp);
    }
    g_Penc[j] = pe0; g_Penc[G4 + j] = pe1;
    g_Pdec[j] = pd0; g_Pdec[G4 + j] = pd1;
    g_startproj[j] = sp;
}

// ---------------- fused gates GEMM + LSTM cell ----------------
// grid 256 blocks x 256 thr: block = 16 b-rows x 32 j-cols x 4 gates, 2 CTAs/SM
__global__ void __launch_bounds__(256, 2) k_lstm_step(const float* __restrict__ rh,
                                                      float* __restrict__ wh,
                                                      const float* __restrict__ W,
                                                      const float* __restrict__ bih,
                                                      const float* __restrict__ bhh,
                                                      const float* __restrict__ inp,
                                                      int t, int is_dec) {
    __shared__ float sA[2][32 * 18];         // [k][b], stride 18
    __shared__ float2 sW01[2][32 * 33];      // [k][j] gate pair {0,1}
    __shared__ float2 sW23[2][32 * 33];      // gate pair {2,3}
    const int tid = threadIdx.x, bid = blockIdx.x;
    const int tx = tid & 31, ty = tid >> 5;          // j lane, row group (0..7)
    const int bm = (bid >> 3) * 16, jn = (bid & 7) * 32;
    const int j = jn + tx;
    const int lrow = tid >> 3;          // 0..31 (W j-row)
    const int lk = (tid & 7) << 2;      // 0,4,..,28
    const int arow = tid >> 3;          // A row if tid<128: 0..15
    const bool aload = tid < 128;

    const float* Ab  = rh + (size_t)(bm + (aload ? arow : 0)) * Hz + lk;
    const float* Wb0 = W + (size_t)(jn + lrow) * Hz + lk;
    const float* Wb1 = Wb0 + (size_t)256 * Hz;
    const float* Wb2 = Wb0 + (size_t)512 * Hz;
    const float* Wb3 = Wb0 + (size_t)768 * Hz;

    float4 pa = aload ? *(const float4*)Ab : make_float4(0.f, 0.f, 0.f, 0.f);
    float4 pw0 = *(const float4*)Wb0;
    float4 pw1 = *(const float4*)Wb1;
    float4 pw2 = *(const float4*)Wb2;
    float4 pw3 = *(const float4*)Wb3;

    u64 acc2[2][2];   // [row r][gate pair]
    acc2[0][0] = pk2(0.f, 0.f); acc2[0][1] = acc2[0][0];
    acc2[1][0] = acc2[0][0];    acc2[1][1] = acc2[0][0];

    for (int k0 = 0; k0 < Hz; k0 += 32) {
        const int buf = (k0 >> 5) & 1;
        float* a_s = sA[buf];
        float2* w01 = sW01[buf];
        float2* w23 = sW23[buf];
        if (aload) {
            a_s[(lk + 0) * 18 + arow] = pa.x;
            a_s[(lk + 1) * 18 + arow] = pa.y;
            a_s[(lk + 2) * 18 + arow] = pa.z;
            a_s[(lk + 3) * 18 + arow] = pa.w;
        }
        {
            const float* p0 = (const float*)&pw0;
            const float* p1 = (const float*)&pw1;
            const float* p2 = (const float*)&pw2;
            const float* p3 = (const float*)&pw3;
#pragma unroll
            for (int i = 0; i < 4; i++) {
                w01[(lk + i) * 33 + lrow] = make_float2(p0[i], p1[i]);
                w23[(lk + i) * 33 + lrow] = make_float2(p2[i], p3[i]);
            }
        }
        __syncthreads();
        if (k0 + 32 < Hz) {
            if (aload) pa = *(const float4*)(Ab + k0 + 32);
            pw0 = *(const float4*)(Wb0 + k0 + 32);
            pw1 = *(const float4*)(Wb1 + k0 + 32);
            pw2 = *(const float4*)(Wb2 + k0 + 32);
            pw3 = *(const float4*)(Wb3 + k0 + 32);
        }
#pragma unroll 8
        for (int k = 0; k < 32; k++) {
            float2 a2 = *(const float2*)&a_s[k * 18 + (ty << 1)];  // broadcast
            u64 wp01 = *(const u64*)&w01[k * 33 + tx];
            u64 wp23 = *(const u64*)&w23[k * 33 + tx];
            u64 ax = pk2(a2.x, a2.x);
            u64 ay = pk2(a2.y, a2.y);
            acc2[0][0] = fma2(wp01, ax, acc2[0][0]);
            acc2[0][1] = fma2(wp23, ax, acc2[0][1]);
            acc2[1][0] = fma2(wp01, ay, acc2[1][0]);
            acc2[1][1] = fma2(wp23, ay, acc2[1][1]);
        }
        __syncthreads();
    }

    const float* P = is_dec ? g_Pdec : g_Penc;
    float xb[4], pb0[4], pb1[4];
#pragma unroll
    for (int g = 0; g < 4; g++) {
        pb0[g] = P[(g << 8) + j];
        pb1[g] = P[G4 + (g << 8) + j];
        xb[g]  = bih[(g << 8) + j] + bhh[(g << 8) + j];
    }
#pragma unroll
    for (int r = 0; r < 2; r++) {
        int b = bm + (ty << 1) + r;
        float a0, a1, a2, a3;
        upk2(acc2[r][0], a0, a1);
        upk2(acc2[r][1], a2, a3);
        float xg[4];
        if (is_dec && t == 0) {
#pragma unroll
            for (int g = 0; g < 4; g++) xg[g] = g_startproj[(g << 8) + j];
        } else {
            int s = is_dec ? g_idx[b] : t;
            float c0 = inp[(b * 2) * Sz + s];
            float c1 = inp[(b * 2 + 1) * Sz + s];
#pragma unroll
            for (int g = 0; g < 4; g++) xg[g] = fmaf(c0, pb0[g], c1 * pb1[g]);
        }
        float gi = a0 + xg[0] + xb[0];
        float gf = a1 + xg[1] + xb[1];
        float gc = a2 + xg[2] + xb[2];
        float go = a3 + xg[3] + xb[3];
        float cc = sigf(gf) * g_c[b * Hz + j] + sigf(gi) * xtanh(gc);
        g_c[b * Hz + j] = cc;
        float hh = sigf(go) * xtanh(cc);
        wh[b * Hz + j] = hh;
        if (!is_dec) g_enc[(size_t)(b * Sz + t) * Hz + j] = hh;
    }
}

// ---------------- ref projections (z=0: glimpse, z=1: pointer) ----------------
__global__ void __launch_bounds__(256) k_ref(const float* __restrict__ gWr,
                                             const float* __restrict__ gbr,
                                             const float* __restrict__ pWr,
                                             const float* __restrict__ pbr) {
    __shared__ float As[16][64];
    __shared__ float Ws[16][64];
    const float* A = g_enc;
    const float* W = blockIdx.z ? pWr : gWr;
    const float* bias = blockIdx.z ? pbr : gbr;
    float* C = blockIdx.z ? g_refp : g_refg;
    const int K = Hz, N = Hz;
    const int bm = blockIdx.y * 64;
    const int bn = blockIdx.x * 64;
    const int t = threadIdx.x;
    const int tx = t & 15, ty = t >> 4;
    const int lr = t >> 2, lc = (t & 3) << 2;
    float acc[4][4];
#pragma unroll
    for (int i = 0; i < 4; i++)
#pragma unroll
        for (int jj = 0; jj < 4; jj++) acc[i][jj] = 0.f;
    const float* Ab = A + (size_t)(bm + lr) * K + lc;
    const float* Wb = W + (size_t)(bn + lr) * K + lc;
    for (int k0 = 0; k0 < K; k0 += 16) {
        float4 av = *(const float4*)(Ab + k0);
        float4 wv = *(const float4*)(Wb + k0);
        As[lc + 0][lr] = av.x; As[lc + 1][lr] = av.y;
        As[lc + 2][lr] = av.z; As[lc + 3][lr] = av.w;
        Ws[lc + 0][lr] = wv.x; Ws[lc + 1][lr] = wv.y;
        Ws[lc + 2][lr] = wv.z; Ws[lc + 3][lr] = wv.w;
        __syncthreads();
#pragma unroll
        for (int k = 0; k < 16; k++) {
            float4 a4 = *(const float4*)&As[k][ty << 2];
            float4 w4 = *(const float4*)&Ws[k][tx << 2];
            float am[4] = {a4.x, a4.y, a4.z, a4.w};
            float wn[4] = {w4.x, w4.y, w4.z, w4.w};
#pragma unroll
            for (int i = 0; i < 4; i++)
#pragma unroll
                for (int jj = 0; jj < 4; jj++)
                    acc[i][jj] = fmaf(am[i], wn[jj], acc[i][jj]);
        }
        __syncthreads();
    }
#pragma unroll
    for (int i = 0; i < 4; i++) {
        int m = bm + (ty << 2) + i;
#pragma unroll
        for (int jj = 0; jj < 4; jj++) {
            int n = bn + (tx << 2) + jj;
            C[(size_t)m * N + n] = acc[i][jj] + bias[n];
        }
    }
}

// warp dual-reduce
__device__ __forceinline__ void wredd(float& a0, float& a1) {
#pragma unroll
    for (int o = 16; o; o >>= 1) {
        a0 += __shfl_xor_sync(0xffffffffu, a0, o);
        a1 += __shfl_xor_sync(0xffffffffu, a1, o);
    }
}

// ---------------- fused decoder attention + sample: TWO b per block, 512 thr ----------------
__global__ void __launch_bounds__(512) k_dec_attn(const float* __restrict__ h,
                                                  const float* __restrict__ gWq,
                                                  const float* __restrict__ gbq,
                                                  const float* __restrict__ gV,
                                                  const float* __restrict__ pWq,
                                                  const float* __restrict__ pbq,
                                                  const float* __restrict__ pV,
                                                  float* __restrict__ out_probs,
                                                  float* __restrict__ out_idx,
                                                  int t) {
    __shared__ __align__(16) float s_h[2][Hz];
    __shared__ __align__(16) float s_qq[2][Hz];
    __shared__ __align__(16) float s_q[2][Hz];
    __shared__ __align__(16) float s_Vg[Hz];
    __shared__ __align__(16) float s_Vp[Hz];
    __shared__ float s_lg[2][128];
    __shared__ float s_w[2][128];
    __shared__ float s_red[2][256];
    __shared__ int s_ridx[2][256];
    __shared__ unsigned char s_m[2][104];

    const int tid = threadIdx.x;
    const int half = tid >> 8;
    const int ht = tid & 255;
    const int b = (blockIdx.x << 1) + half;
    const int b0 = (blockIdx.x << 1), b1 = b0 + 1;
    const int wd = tid >> 5;    // 0..15
    const int ln = tid & 31;

    if (t > 0 && ht == 0) g_mask[b * Sz + g_idx[b]] = 1;
    __syncthreads();
    if (ht < Sz) s_m[half][ht] = g_mask[b * Sz + ht];
    s_h[half][ht] = h[b * Hz + ht];
    if (tid < Hz) s_Vg[tid] = gV[tid];
    else if (tid < 2 * Hz) s_Vp[tid - Hz] = pV[tid - Hz];
    __syncthreads();

    // qq = h @ gWq^T + gbq, warp-cooperative rows (coalesced W reads, both b's)
    for (int row = wd; row < Hz; row += 16) {
        const float4* wr = (const float4*)(gWq + (size_t)row * Hz);
        float4 w1 = wr[ln], w2 = wr[32 + ln];
        float4 ha = *(const float4*)&s_h[0][ln << 2];
        float4 hb = *(const float4*)&s_h[0][128 + (ln << 2)];
        float4 hc = *(const float4*)&s_h[1][ln << 2];
        float4 hd = *(const float4*)&s_h[1][128 + (ln << 2)];
        float a0 = 0.f, a1 = 0.f;
        a0 = fmaf(w1.x, ha.x, a0); a0 = fmaf(w1.y, ha.y, a0);
        a0 = fmaf(w1.z, ha.z, a0); a0 = fmaf(w1.w, ha.w, a0);
        a0 = fmaf(w2.x, hb.x, a0); a0 = fmaf(w2.y, hb.y, a0);
        a0 = fmaf(w2.z, hb.z, a0); a0 = fmaf(w2.w, hb.w, a0);
        a1 = fmaf(w1.x, hc.x, a1); a1 = fmaf(w1.y, hc.y, a1);
        a1 = fmaf(w1.z, hc.z, a1); a1 = fmaf(w1.w, hc.w, a1);
        a1 = fmaf(w2.x, hd.x, a1); a1 = fmaf(w2.y, hd.y, a1);
        a1 = fmaf(w2.z, hd.z, a1); a1 = fmaf(w2.w, hd.w, a1);
        wredd(a0, a1);
        if (!ln) {
            float bq = gbq[row];
            s_qq[0][row] = a0 + bq;
            s_qq[1][row] = a1 + bq;
        }
    }
    __syncthreads();
    // glimpse logits: warp handles one s for BOTH b's
    for (int s = wd; s < Sz; s += 16) {
        const bool m0 = s_m[0][s], m1 = s_m[1][s];
        float a0 = 0.f, a1 = 0.f;
        if (!m0) {
            const float4* rg = (const float4*)(g_refg + ((size_t)b0 * Sz + s) * Hz);
#pragma unroll
            for (int i = 0; i < 2; i++) {
                int c = i * 32 + ln;
                float4 rv = rg[c];
                float4 qv = *(const float4*)&s_qq[0][c << 2];
                float4 vv = *(const float4*)&s_Vg[c << 2];
                a0 = fmaf(vv.x, xtanh(qv.x + rv.x), a0);
                a0 = fmaf(vv.y, xtanh(qv.y + rv.y), a0);
                a0 = fmaf(vv.z, xtanh(qv.z + rv.z), a0);
                a0 = fmaf(vv.w, xtanh(qv.w + rv.w), a0);
            }
        }
        if (!m1) {
            const float4* rg = (const float4*)(g_refg + ((size_t)b1 * Sz + s) * Hz);
#pragma unroll
            for (int i = 0; i < 2; i++) {
                int c = i * 32 + ln;
                float4 rv = rg[c];
                float4 qv = *(const float4*)&s_qq[1][c << 2];
                float4 vv = *(const float4*)&s_Vg[c << 2];
                a1 = fmaf(vv.x, xtanh(qv.x + rv.x), a1);
                a1 = fmaf(vv.y, xtanh(qv.y + rv.y), a1);
                a1 = fmaf(vv.z, xtanh(qv.z + rv.z), a1);
                a1 = fmaf(vv.w, xtanh(qv.w + rv.w), a1);
            }
        }
        wredd(a0, a1);
        if (!ln) {
            s_lg[0][s] = m0 ? -INFINITY : a0;
            s_lg[1][s] = m1 ? -INFINITY : a1;
        }
    }
    __syncthreads();
    // softmax -> s_w
    {
        float v = (ht < Sz) ? s_lg[half][ht] : -INFINITY;
        s_red[half][ht] = v; __syncthreads();
#pragma unroll
        for (int o = 128; o; o >>= 1) { if (ht < o) s_red[half][ht] = fmaxf(s_red[half][ht], s_red[half][ht + o]); __syncthreads(); }
        float m = s_red[half][0]; __syncthreads();
        float e = (ht < Sz) ? expf(v - m) : 0.f;
        s_red[half][ht] = e; __syncthreads();
#pragma unroll
        for (int o = 128; o; o >>= 1) { if (ht < o) s_red[half][ht] += s_red[half][ht + o]; __syncthreads(); }
        float sm = s_red[half][0]; __syncthreads();
        if (ht < 128) s_w[half][ht] = (ht < Sz) ? e / sm : 0.f;
    }
    __syncthreads();
    // q = sum_s w[s] * enc[b,s,:], MLP=8
    {
        float av[8];
#pragma unroll
        for (int i = 0; i < 8; i++) av[i] = 0.f;
        const float* eb = g_enc + (size_t)b * Sz * Hz + ht;
        int s = 0;
        for (; s + 8 <= Sz; s += 8) {
#pragma unroll
            for (int i = 0; i < 8; i++)
                av[i] = fmaf(s_w[half][s + i], eb[(size_t)(s + i) * Hz], av[i]);
        }
#pragma unroll
        for (int i = 0; i < 4; i++)
            av[i] = fmaf(s_w[half][s + i], eb[(size_t)(s + i) * Hz], av[i]);
        s_q[half][ht] = ((av[0] + av[1]) + (av[2] + av[3])) + ((av[4] + av[5]) + (av[6] + av[7]));
    }
    __syncthreads();
    // qq2 = q @ pWq^T + pbq (warp-cooperative)
    for (int row = wd; row < Hz; row += 16) {
        const float4* wr = (const float4*)(pWq + (size_t)row * Hz);
        float4 w1 = wr[ln], w2 = wr[32 + ln];
        float4 ha = *(const float4*)&s_q[0][ln << 2];
        float4 hb = *(const float4*)&s_q[0][128 + (ln << 2)];
        float4 hc = *(const float4*)&s_q[1][ln << 2];
        float4 hd = *(const float4*)&s_q[1][128 + (ln << 2)];
        float a0 = 0.f, a1 = 0.f;
        a0 = fmaf(w1.x, ha.x, a0); a0 = fmaf(w1.y, ha.y, a0);
        a0 = fmaf(w1.z, ha.z, a0); a0 = fmaf(w1.w, ha.w, a0);
        a0 = fmaf(w2.x, hb.x, a0); a0 = fmaf(w2.y, hb.y, a0);
        a0 = fmaf(w2.z, hb.z, a0); a0 = fmaf(w2.w, hb.w, a0);
        a1 = fmaf(w1.x, hc.x, a1); a1 = fmaf(w1.y, hc.y, a1);
        a1 = fmaf(w1.z, hc.z, a1); a1 = fmaf(w1.w, hc.w, a1);
        a1 = fmaf(w2.x, hd.x, a1); a1 = fmaf(w2.y, hd.y, a1);
        a1 = fmaf(w2.z, hd.z, a1); a1 = fmaf(w2.w, hd.w, a1);
        wredd(a0, a1);
        if (!ln) {
            float bq = pbq[row];
            s_qq[0][row] = a0 + bq;
            s_qq[1][row] = a1 + bq;
        }
    }
    __syncthreads();
    // pointer logits
    for (int s = wd; s < Sz; s += 16) {
        const bool m0 = s_m[0][s], m1 = s_m[1][s];
        float a0 = 0.f, a1 = 0.f;
        if (!m0) {
            const float4* rp = (const float4*)(g_refp + ((size_t)b0 * Sz + s) * Hz);
#pragma unroll
            for (int i = 0; i < 2; i++) {
                int c = i * 32 + ln;
                float4 rv = rp[c];
                float4 qv = *(const float4*)&s_qq[0][c << 2];
                float4 vv = *(const float4*)&s_Vp[c << 2];
                a0 = fmaf(vv.x, xtanh(qv.x + rv.x), a0);
                a0 = fmaf(vv.y, xtanh(qv.y + rv.y), a0);
                a0 = fmaf(vv.z, xtanh(qv.z + rv.z), a0);
                a0 = fmaf(vv.w, xtanh(qv.w + rv.w), a0);
            }
        }
        if (!m1) {
            const float4* rp = (const float4*)(g_refp + ((size_t)b1 * Sz + s) * Hz);
#pragma unroll
            for (int i = 0; i < 2; i++) {
                int c = i * 32 + ln;
                float4 rv = rp[c];
                float4 qv = *(const float4*)&s_qq[1][c << 2];
                float4 vv = *(const float4*)&s_Vp[c << 2];
                a1 = fmaf(vv.x, xtanh(qv.x + rv.x), a1);
                a1 = fmaf(vv.y, xtanh(qv.y + rv.y), a1);
                a1 = fmaf(vv.z, xtanh(qv.z + rv.z), a1);
                a1 = fmaf(vv.w, xtanh(qv.w + rv.w), a1);
            }
        }
        wredd(a0, a1);
        if (!ln) {
            s_lg[0][s] = m0 ? -INFINITY : C_EXPLORE * xtanh(a0);
            s_lg[1][s] = m1 ? -INFINITY : C_EXPLORE * xtanh(a1);
        }
    }
    __syncthreads();
    // softmax -> probs; gumbel argmax -> idx
    {
        float v = (ht < Sz) ? s_lg[half][ht] : -INFINITY;
        s_red[half][ht] = v; __syncthreads();
#pragma unroll
        for (int o = 128; o; o >>= 1) { if (ht < o) s_red[half][ht] = fmaxf(s_red[half][ht], s_red[half][ht + o]); __syncthreads(); }
        float m = s_red[half][0]; __syncthreads();
        float e = (ht < Sz) ? expf(v - m) : 0.f;
        s_red[half][ht] = e; __syncthreads();
#pragma unroll
        for (int o = 128; o; o >>= 1) { if (ht < o) s_red[half][ht] += s_red[half][ht + o]; __syncthreads(); }
        float sm = s_red[half][0]; __syncthreads();
        if (ht < Sz)
            out_probs[(size_t)b * Sz + ht] = e / sm;
        float pv = -INFINITY;
        if (ht < Sz) {
            unsigned key0, key1;
#if PARTITIONABLE
            tf2x32(0u, 1u, 0u, (unsigned)t, key0, key1);
#else
            {
                unsigned a0k, b0k;
                unsigned idx0 = 2u * t, idx1 = 2u * t + 1u;
                if (idx0 < Sz) { tf2x32(0u, 1u, idx0, idx0 + Sz, a0k, b0k); key0 = a0k; }
                else           { tf2x32(0u, 1u, idx0 - Sz, idx0, a0k, b0k); key0 = b0k; }
                if (idx1 < Sz) { tf2x32(0u, 1u, idx1, idx1 + Sz, a0k, b0k); key1 = a0k; }
                else           { tf2x32(0u, 1u, idx1 - Sz, idx1, a0k, b0k); key1 = b0k; }
            }
#endif
            unsigned m0 = (unsigned)(b * Sz + ht);
            unsigned ra, rb, bits;
#if PARTITIONABLE
            tf2x32(key0, key1, 0u, m0, ra, rb);
            bits = ra ^ rb;
#else
            const unsigned halfn = (Bz * Sz) / 2;
            if (m0 < halfn) { tf2x32(key0, key1, m0, m0 + halfn, ra, rb); bits = ra; }
            else            { tf2x32(key0, key1, m0 - halfn, m0, ra, rb); bits = rb; }
#endif
            float f = __uint_as_float((bits >> 9) | 0x3f800000u) - 1.0f;
            float u = fmaxf(f, 1.17549435e-38f);
            pv = v - logf(-logf(u));
        }
        s_red[half][ht] = pv; s_ridx[half][ht] = ht; __syncthreads();
#pragma unroll
        for (int o = 128; o; o >>= 1) {
            if (ht < o) {
                float a2 = s_red[half][ht], c2 = s_red[half][ht + o];
                int ia = s_ridx[half][ht], ic = s_ridx[half][ht + o];
                if (c2 > a2 || (c2 == a2 && ic < ia)) { s_red[half][ht] = c2; s_ridx[half][ht] = ic; }
            }
            __syncthreads();
        }
        if (!ht) {
            int id = s_ridx[half][0];
            g_idx[b] = id;
            out_idx[b] = (float)id;
        }
    }
}

// ---------------- host ----------------
template <typename T>
static T* symaddr(const void* sym) {
    void* p = nullptr;
    cudaGetSymbolAddress(&p, sym);
    return (T*)p;
}

extern "C" void kernel_launch(void* const* d_in, const int* in_sizes, int n_in,
                              void* d_out, int out_size) {
    const float* in_inputs = (const float*)d_in[0];
    const float* in_emb    = (const float*)d_in[1];
    const float* in_eWih   = (const float*)d_in[2];
    const float* in_eWhh   = (const float*)d_in[3];
    const float* in_ebih   = (const float*)d_in[4];
    const float* in_ebhh   = (const float*)d_in[5];
    const float* in_dWih   = (const float*)d_in[6];
    const float* in_dWhh   = (const float*)d_in[7];
    const float* in_dbih   = (const float*)d_in[8];
    const float* in_dbhh   = (const float*)d_in[9];
    const float* in_gWq    = (const float*)d_in[10];
    const float* in_gbq    = (const float*)d_in[11];
    const float* in_gWr    = (const float*)d_in[12];
    const float* in_gbr    = (const float*)d_in[13];
    const float* in_gV     = (const float*)d_in[14];
    const float* in_pWq    = (const float*)d_in[15];
    const float* in_pbq    = (const float*)d_in[16];
    const float* in_pWr    = (const float*)d_in[17];
    const float* in_pbr    = (const float*)d_in[18];
    const float* in_pV     = (const float*)d_in[19];
    const float* in_start  = (const float*)d_in[20];
    float* out = (float*)d_out;

    float* p_h0 = symaddr<float>(g_h0);
    float* p_h1 = symaddr<float>(g_h1);

    k_init<<<512, 256>>>();
    k_prep<<<4, 256>>>(in_emb, in_eWih, in_dWih, in_start);

    for (int t = 0; t < Sz; t++) {
        const float* rh = (t & 1) ? p_h1 : p_h0;
        float* wh       = (t & 1) ? p_h0 : p_h1;
        k_lstm_step<<<256, 256>>>(rh, wh, in_eWhh, in_ebih, in_ebhh, in_inputs, t, 0);
    }

    {
        dim3 grid(Hz / 64, (Bz * Sz) / 64, 2);
        k_ref<<<grid, 256>>>(in_gWr, in_gbr, in_pWr, in_pbr);
    }

    float* out_probs = out;
    float* out_idx = out + (size_t)Sz * Bz * Sz;
    for (int t = 0; t < Sz; t++) {
        const float* rh = (t & 1) ? p_h1 : p_h0;
        float* wh       = (t & 1) ? p_h0 : p_h1;
        k_lstm_step<<<256, 256>>>(rh, wh, in_dWhh, in_dbih, in_dbhh, in_inputs, t, 1);
        k_dec_attn<<<Bz / 2, 512>>>(wh, in_gWq, in_gbq, in_gV, in_pWq, in_pbq, in_pV,
                                    out_probs + (size_t)t * Bz * Sz,
                                    out_idx + (size_t)t * Bz, t);
    }
    (void)in_sizes; (void)n_in; (void)out_size;
}

// round 10
// speedup vs baseline: 1.3365x; 1.1351x over previous
#include <cuda_runtime.h>
#include <cuda_bf16.h>
#include <math.h>
#include <stdint.h>

#define Bz 512
#define Sz 100
#define Ez 256
#define Hz 256
#define G4 1024
#define C_EXPLORE 10.0f
#define PARTITIONABLE 1

typedef unsigned long long u64;

// ---------------- packed f32x2 helpers (sm_100+) ----------------
__device__ __forceinline__ u64 pk2(float lo, float hi) {
    u64 d; asm("mov.b64 %0, {%1, %2};" : "=l"(d) : "f"(lo), "f"(hi)); return d;
}
__device__ __forceinline__ void upk2(u64 v, float& lo, float& hi) {
    asm("mov.b64 {%0, %1}, %2;" : "=f"(lo), "=f"(hi) : "l"(v));
}
__device__ __forceinline__ u64 fma2(u64 a, u64 b, u64 c) {
    u64 d; asm("fma.rn.f32x2 %0, %1, %2, %3;" : "=l"(d) : "l"(a), "l"(b), "l"(c)); return d;
}

// ---------------- fast exact-enough tanh (Eigen/XLA rational + rcp NR) ----------------
__device__ __forceinline__ float xtanh(float x) {
    const float c = 7.90531110763549805f;
    float cx = fminf(fmaxf(x, -c), c);
    float r = cx * cx;
    float p = -2.76076847742355e-16f;
    p = fmaf(p, r, 2.00018790482477e-13f);
    p = fmaf(p, r, -8.60467152213735e-11f);
    p = fmaf(p, r, 5.12229709037114e-08f);
    p = fmaf(p, r, 1.48572235717979e-05f);
    p = fmaf(p, r, 6.37261928875436e-04f);
    p = fmaf(p, r, 4.89352455891786e-03f);
    float num = cx * p;
    float q = 1.19825839466702e-06f;
    q = fmaf(q, r, 1.18534705686654e-04f);
    q = fmaf(q, r, 2.26843463243900e-03f);
    q = fmaf(q, r, 4.89352518554385e-03f);
    float ri;
    asm("rcp.approx.f32 %0, %1;" : "=f"(ri) : "f"(q));
    ri = ri * fmaf(-q, ri, 2.0f);
    return num * ri;
}
__device__ __forceinline__ float sigf(float x) {
    return 0.5f + 0.5f * xtanh(0.5f * x);
}

// ---------------- device state ----------------
__device__ float g_h0[Bz * Hz];
__device__ float g_h1[Bz * Hz];
__device__ float g_c[Bz * Hz];
__device__ float g_enc[(size_t)Bz * Sz * Hz];
__device__ float g_refg[(size_t)Bz * Sz * Hz];
__device__ float g_refp[(size_t)Bz * Sz * Hz];
__device__ float g_Penc[2 * G4];
__device__ float g_Pdec[2 * G4];
__device__ float g_startproj[G4];
__device__ int g_idx[Bz];
__device__ unsigned char g_mask[Bz * Sz];

// ---------------- threefry2x32 ----------------
__device__ __forceinline__ unsigned rotl32(unsigned v, int r) {
    return (v << r) | (v >> (32 - r));
}
__device__ __forceinline__ void tf2x32(unsigned k0, unsigned k1,
                                       unsigned x0, unsigned x1,
                                       unsigned& o0, unsigned& o1) {
    unsigned ks2 = 0x1BD11BDAu ^ k0 ^ k1;
    x0 += k0; x1 += k1;
#define TF_G(a,b,c,d) \
    x0 += x1; x1 = rotl32(x1,a); x1 ^= x0; \
    x0 += x1; x1 = rotl32(x1,b); x1 ^= x0; \
    x0 += x1; x1 = rotl32(x1,c); x1 ^= x0; \
    x0 += x1; x1 = rotl32(x1,d); x1 ^= x0;
    TF_G(13,15,26,6);  x0 += k1;  x1 += ks2 + 1u;
    TF_G(17,29,16,24); x0 += ks2; x1 += k0 + 2u;
    TF_G(13,15,26,6);  x0 += k0;  x1 += k1 + 3u;
    TF_G(17,29,16,24); x0 += k1;  x1 += ks2 + 4u;
    TF_G(13,15,26,6);  x0 += ks2; x1 += k0 + 5u;
#undef TF_G
    o0 = x0; o1 = x1;
}

// ---------------- setup ----------------
__global__ void k_init() {
    int i = blockIdx.x * blockDim.x + threadIdx.x;
    if (i < Bz * Hz) { g_h0[i] = 0.f; g_c[i] = 0.f; }
    if (i < Bz * Sz) g_mask[i] = 0;
    if (i < Bz) g_idx[i] = 0;
}

__global__ void k_prep(const float* __restrict__ emb,
                       const float* __restrict__ eWih,
                       const float* __restrict__ dWih,
                       const float* __restrict__ start) {
    int j = blockIdx.x * 256 + threadIdx.x;
    if (j >= G4) return;
    float pe0 = 0.f, pe1 = 0.f, pd0 = 0.f, pd1 = 0.f, sp = 0.f;
    for (int e = 0; e < Ez; e++) {
        float we = eWih[j * Ez + e], wd = dWih[j * Ez + e];
        pe0 = fmaf(emb[e], we, pe0);
        pe1 = fmaf(emb[Ez + e], we, pe1);
        pd0 = fmaf(emb[e], wd, pd0);
        pd1 = fmaf(emb[Ez + e], wd, pd1);
        sp  = fmaf(start[e], wd, sp);
    }
    g_Penc[j] = pe0; g_Penc[G4 + j] = pe1;
    g_Pdec[j] = pd0; g_Pdec[G4 + j] = pd1;
    g_startproj[j] = sp;
}

// ---------------- fused gates GEMM + LSTM cell (R8 config: 128 blocks, 32b x 32j) ----------------
__global__ void __launch_bounds__(256) k_lstm_step(const float* __restrict__ rh,
                                                   float* __restrict__ wh,
                                                   const float* __restrict__ W,
                                                   const float* __restrict__ bih,
                                                   const float* __restrict__ bhh,
                                                   const float* __restrict__ inp,
                                                   int t, int is_dec) {
    __shared__ float sA[2][32 * 36];
    __shared__ float2 sW01[2][32 * 33];
    __shared__ float2 sW23[2][32 * 33];
    const int tid = threadIdx.x, bid = blockIdx.x;
    const int tx = tid & 31, ty = tid >> 5;
    const int bm = (bid >> 3) * 32, jn = (bid & 7) * 32;
    const int j = jn + tx;
    const int lrow = tid >> 3;
    const int lk = (tid & 7) << 2;

    const float* Ab  = rh + (size_t)(bm + lrow) * Hz + lk;
    const float* Wb0 = W + (size_t)(jn + lrow) * Hz + lk;
    const float* Wb1 = Wb0 + (size_t)256 * Hz;
    const float* Wb2 = Wb0 + (size_t)512 * Hz;
    const float* Wb3 = Wb0 + (size_t)768 * Hz;

    float4 pa  = *(const float4*)Ab;
    float4 pw0 = *(const float4*)Wb0;
    float4 pw1 = *(const float4*)Wb1;
    float4 pw2 = *(const float4*)Wb2;
    float4 pw3 = *(const float4*)Wb3;

    u64 acc2[4][2];
#pragma unroll
    for (int r = 0; r < 4; r++) { acc2[r][0] = pk2(0.f, 0.f); acc2[r][1] = acc2[r][0]; }

    for (int k0 = 0; k0 < Hz; k0 += 32) {
        const int buf = (k0 >> 5) & 1;
        float* a_s = sA[buf];
        float2* w01 = sW01[buf];
        float2* w23 = sW23[buf];
        a_s[(lk + 0) * 36 + lrow] = pa.x;
        a_s[(lk + 1) * 36 + lrow] = pa.y;
        a_s[(lk + 2) * 36 + lrow] = pa.z;
        a_s[(lk + 3) * 36 + lrow] = pa.w;
        {
            const float* p0 = (const float*)&pw0;
            const float* p1 = (const float*)&pw1;
            const float* p2 = (const float*)&pw2;
            const float* p3 = (const float*)&pw3;
#pragma unroll
            for (int i = 0; i < 4; i++) {
                w01[(lk + i) * 33 + lrow] = make_float2(p0[i], p1[i]);
                w23[(lk + i) * 33 + lrow] = make_float2(p2[i], p3[i]);
            }
        }
        __syncthreads();
        if (k0 + 32 < Hz) {
            pa  = *(const float4*)(Ab + k0 + 32);
            pw0 = *(const float4*)(Wb0 + k0 + 32);
            pw1 = *(const float4*)(Wb1 + k0 + 32);
            pw2 = *(const float4*)(Wb2 + k0 + 32);
            pw3 = *(const float4*)(Wb3 + k0 + 32);
        }
#pragma unroll 8
        for (int k = 0; k < 32; k++) {
            float4 a4 = *(const float4*)&sA[buf][k * 36 + (ty << 2)];
            u64 wp01 = *(const u64*)&w01[k * 33 + tx];
            u64 wp23 = *(const u64*)&w23[k * 33 + tx];
            u64 ax = pk2(a4.x, a4.x);
            u64 ay = pk2(a4.y, a4.y);
            u64 az = pk2(a4.z, a4.z);
            u64 aw = pk2(a4.w, a4.w);
            acc2[0][0] = fma2(wp01, ax, acc2[0][0]);
            acc2[0][1] = fma2(wp23, ax, acc2[0][1]);
            acc2[1][0] = fma2(wp01, ay, acc2[1][0]);
            acc2[1][1] = fma2(wp23, ay, acc2[1][1]);
            acc2[2][0] = fma2(wp01, az, acc2[2][0]);
            acc2[2][1] = fma2(wp23, az, acc2[2][1]);
            acc2[3][0] = fma2(wp01, aw, acc2[3][0]);
            acc2[3][1] = fma2(wp23, aw, acc2[3][1]);
        }
        __syncthreads();
    }

    const float* P = is_dec ? g_Pdec : g_Penc;
    float xb[4], pb0[4], pb1[4];
#pragma unroll
    for (int g = 0; g < 4; g++) {
        pb0[g] = P[(g << 8) + j];
        pb1[g] = P[G4 + (g << 8) + j];
        xb[g]  = bih[(g << 8) + j] + bhh[(g << 8) + j];
    }
#pragma unroll
    for (int r = 0; r < 4; r++) {
        int b = bm + (ty << 2) + r;
        float a0, a1, a2, a3;
        upk2(acc2[r][0], a0, a1);
        upk2(acc2[r][1], a2, a3);
        float xg[4];
        if (is_dec && t == 0) {
#pragma unroll
            for (int g = 0; g < 4; g++) xg[g] = g_startproj[(g << 8) + j];
        } else {
            int s = is_dec ? g_idx[b] : t;
            float c0 = inp[(b * 2) * Sz + s];
            float c1 = inp[(b * 2 + 1) * Sz + s];
#pragma unroll
            for (int g = 0; g < 4; g++) xg[g] = fmaf(c0, pb0[g], c1 * pb1[g]);
        }
        float gi = a0 + xg[0] + xb[0];
        float gf = a1 + xg[1] + xb[1];
        float gc = a2 + xg[2] + xb[2];
        float go = a3 + xg[3] + xb[3];
        float cc = sigf(gf) * g_c[b * Hz + j] + sigf(gi) * xtanh(gc);
        g_c[b * Hz + j] = cc;
        float hh = sigf(go) * xtanh(cc);
        wh[b * Hz + j] = hh;
        if (!is_dec) g_enc[(size_t)(b * Sz + t) * Hz + j] = hh;
    }
}

// ---------------- ref projections (z=0: glimpse, z=1: pointer) ----------------
__global__ void __launch_bounds__(256) k_ref(const float* __restrict__ gWr,
                                             const float* __restrict__ gbr,
                                             const float* __restrict__ pWr,
                                             const float* __restrict__ pbr) {
    __shared__ float As[16][64];
    __shared__ float Ws[16][64];
    const float* A = g_enc;
    const float* W = blockIdx.z ? pWr : gWr;
    const float* bias = blockIdx.z ? pbr : gbr;
    float* C = blockIdx.z ? g_refp : g_refg;
    const int K = Hz, N = Hz;
    const int bm = blockIdx.y * 64;
    const int bn = blockIdx.x * 64;
    const int t = threadIdx.x;
    const int tx = t & 15, ty = t >> 4;
    const int lr = t >> 2, lc = (t & 3) << 2;
    float acc[4][4];
#pragma unroll
    for (int i = 0; i < 4; i++)
#pragma unroll
        for (int jj = 0; jj < 4; jj++) acc[i][jj] = 0.f;
    const float* Ab = A + (size_t)(bm + lr) * K + lc;
    const float* Wb = W + (size_t)(bn + lr) * K + lc;
    for (int k0 = 0; k0 < K; k0 += 16) {
        float4 av = *(const float4*)(Ab + k0);
        float4 wv = *(const float4*)(Wb + k0);
        As[lc + 0][lr] = av.x; As[lc + 1][lr] = av.y;
        As[lc + 2][lr] = av.z; As[lc + 3][lr] = av.w;
        Ws[lc + 0][lr] = wv.x; Ws[lc + 1][lr] = wv.y;
        Ws[lc + 2][lr] = wv.z; Ws[lc + 3][lr] = wv.w;
        __syncthreads();
#pragma unroll
        for (int k = 0; k < 16; k++) {
            float4 a4 = *(const float4*)&As[k][ty << 2];
            float4 w4 = *(const float4*)&Ws[k][tx << 2];
            float am[4] = {a4.x, a4.y, a4.z, a4.w};
            float wn[4] = {w4.x, w4.y, w4.z, w4.w};
#pragma unroll
            for (int i = 0; i < 4; i++)
#pragma unroll
                for (int jj = 0; jj < 4; jj++)
                    acc[i][jj] = fmaf(am[i], wn[jj], acc[i][jj]);
        }
        __syncthreads();
    }
#pragma unroll
    for (int i = 0; i < 4; i++) {
        int m = bm + (ty << 2) + i;
#pragma unroll
        for (int jj = 0; jj < 4; jj++) {
            int n = bn + (tx << 2) + jj;
            C[(size_t)m * N + n] = acc[i][jj] + bias[n];
        }
    }
}

// warp dual-reduce
__device__ __forceinline__ void wredd(float& a0, float& a1) {
#pragma unroll
    for (int o = 16; o; o >>= 1) {
        a0 += __shfl_xor_sync(0xffffffffu, a0, o);
        a1 += __shfl_xor_sync(0xffffffffu, a1, o);
    }
}

// ---------------- fused decoder attention + sample: TWO b per block, 512 thr ----------------
__global__ void __launch_bounds__(512) k_dec_attn(const float* __restrict__ h,
                                                  const float* __restrict__ gWq,
                                                  const float* __restrict__ gbq,
                                                  const float* __restrict__ gV,
                                                  const float* __restrict__ pWq,
                                                  const float* __restrict__ pbq,
                                                  const float* __restrict__ pV,
                                                  float* __restrict__ out_probs,
                                                  float* __restrict__ out_idx,
                                                  int t) {
    __shared__ __align__(16) float s_h[2][Hz];
    __shared__ __align__(16) float s_qq[2][Hz];
    __shared__ __align__(16) float s_q[2][Hz];
    __shared__ __align__(16) float s_Vg[Hz];
    __shared__ __align__(16) float s_Vp[Hz];
    __shared__ float s_lg[2][128];
    __shared__ float s_w[2][128];
    __shared__ float s_red[2][256];
    __shared__ int s_ridx[2][256];
    __shared__ unsigned char s_m[2][104];
    __shared__ short s_list[2][104];
    __shared__ int s_ccnt[2][4];

    const int tid = threadIdx.x;
    const int half = tid >> 8;
    const int ht = tid & 255;
    const int b = (blockIdx.x << 1) + half;
    const int b0 = (blockIdx.x << 1), b1 = b0 + 1;
    const int wd = tid >> 5;    // 0..15
    const int ln = tid & 31;

    if (t > 0 && ht == 0) g_mask[b * Sz + g_idx[b]] = 1;
    __syncthreads();
    if (ht < Sz) s_m[half][ht] = g_mask[b * Sz + ht];
    s_h[half][ht] = h[b * Hz + ht];
    if (tid < Hz) s_Vg[tid] = gV[tid];
    else if (tid < 2 * Hz) s_Vp[tid - Hz] = pV[tid - Hz];
    __syncthreads();

    // ---- deterministic compaction of unmasked s (ascending) ----
    bool un = false; int pre = 0, chunk = 0;
    if (ht < 128) {
        chunk = ht >> 5;
        un = (ht < Sz) && !s_m[half][ht];
        unsigned bal = __ballot_sync(0xffffffffu, un);
        pre = __popc(bal & ((1u << (ht & 31)) - 1));
        if ((ht & 31) == 0) s_ccnt[half][chunk] = __popc(bal);
    }
    __syncthreads();
    const int n_half = s_ccnt[half][0] + s_ccnt[half][1] + s_ccnt[half][2] + s_ccnt[half][3];
    const int n0 = s_ccnt[0][0] + s_ccnt[0][1] + s_ccnt[0][2] + s_ccnt[0][3];
    const int n1 = s_ccnt[1][0] + s_ccnt[1][1] + s_ccnt[1][2] + s_ccnt[1][3];
    const int nmax = n0 > n1 ? n0 : n1;
    if (un) {
        int base = 0;
        for (int i = 0; i < chunk; i++) base += s_ccnt[half][i];
        s_list[half][base + pre] = (short)ht;
    }
    if (ht < 128) s_lg[half][ht] = -INFINITY;
    __syncthreads();

    // qq = h @ gWq^T + gbq, warp-cooperative rows (both b's)
    for (int row = wd; row < Hz; row += 16) {
        const float4* wr = (const float4*)(gWq + (size_t)row * Hz);
        float4 w1 = wr[ln], w2 = wr[32 + ln];
        float4 ha = *(const float4*)&s_h[0][ln << 2];
        float4 hb = *(const float4*)&s_h[0][128 + (ln << 2)];
        float4 hc = *(const float4*)&s_h[1][ln << 2];
        float4 hd = *(const float4*)&s_h[1][128 + (ln << 2)];
        float a0 = 0.f, a1 = 0.f;
        a0 = fmaf(w1.x, ha.x, a0); a0 = fmaf(w1.y, ha.y, a0);
        a0 = fmaf(w1.z, ha.z, a0); a0 = fmaf(w1.w, ha.w, a0);
        a0 = fmaf(w2.x, hb.x, a0); a0 = fmaf(w2.y, hb.y, a0);
        a0 = fmaf(w2.z, hb.z, a0); a0 = fmaf(w2.w, hb.w, a0);
        a1 = fmaf(w1.x, hc.x, a1); a1 = fmaf(w1.y, hc.y, a1);
        a1 = fmaf(w1.z, hc.z, a1); a1 = fmaf(w1.w, hc.w, a1);
        a1 = fmaf(w2.x, hd.x, a1); a1 = fmaf(w2.y, hd.y, a1);
        a1 = fmaf(w2.z, hd.z, a1); a1 = fmaf(w2.w, hd.w, a1);
        wredd(a0, a1);
        if (!ln) {
            float bq = gbq[row];
            s_qq[0][row] = a0 + bq;
            s_qq[1][row] = a1 + bq;
        }
    }
    __syncthreads();
    // glimpse logits over compact lists
    for (int ii = wd; ii < nmax; ii += 16) {
        int s0 = (ii < n0) ? s_list[0][ii] : -1;
        int s1 = (ii < n1) ? s_list[1][ii] : -1;
        float a0 = 0.f, a1 = 0.f;
        if (s0 >= 0) {
            const float4* rg = (const float4*)(g_refg + ((size_t)b0 * Sz + s0) * Hz);
#pragma unroll
            for (int i = 0; i < 2; i++) {
                int c = i * 32 + ln;
                float4 rv = rg[c];
                float4 qv = *(const float4*)&s_qq[0][c << 2];
                float4 vv = *(const float4*)&s_Vg[c << 2];
                a0 = fmaf(vv.x, xtanh(qv.x + rv.x), a0);
                a0 = fmaf(vv.y, xtanh(qv.y + rv.y), a0);
                a0 = fmaf(vv.z, xtanh(qv.z + rv.z), a0);
                a0 = fmaf(vv.w, xtanh(qv.w + rv.w), a0);
            }
        }
        if (s1 >= 0) {
            const float4* rg = (const float4*)(g_refg + ((size_t)b1 * Sz + s1) * Hz);
#pragma unroll
            for (int i = 0; i < 2; i++) {
                int c = i * 32 + ln;
                float4 rv = rg[c];
                float4 qv = *(const float4*)&s_qq[1][c << 2];
                float4 vv = *(const float4*)&s_Vg[c << 2];
                a1 = fmaf(vv.x, xtanh(qv.x + rv.x), a1);
                a1 = fmaf(vv.y, xtanh(qv.y + rv.y), a1);
                a1 = fmaf(vv.z, xtanh(qv.z + rv.z), a1);
                a1 = fmaf(vv.w, xtanh(qv.w + rv.w), a1);
            }
        }
        wredd(a0, a1);
        if (!ln) {
            if (s0 >= 0) s_lg[0][s0] = a0;
            if (s1 >= 0) s_lg[1][s1] = a1;
        }
    }
    __syncthreads();
    // softmax -> s_w
    {
        float v = (ht < Sz) ? s_lg[half][ht] : -INFINITY;
        s_red[half][ht] = v; __syncthreads();
#pragma unroll
        for (int o = 128; o; o >>= 1) { if (ht < o) s_red[half][ht] = fmaxf(s_red[half][ht], s_red[half][ht + o]); __syncthreads(); }
        float m = s_red[half][0]; __syncthreads();
        float e = (ht < Sz) ? expf(v - m) : 0.f;
        s_red[half][ht] = e; __syncthreads();
#pragma unroll
        for (int o = 128; o; o >>= 1) { if (ht < o) s_red[half][ht] += s_red[half][ht + o]; __syncthreads(); }
        float sm = s_red[half][0]; __syncthreads();
        if (ht < 128) s_w[half][ht] = (ht < Sz) ? e / sm : 0.f;
    }
    __syncthreads();
    // q = sum over UNMASKED s of w[s]*enc[b,s,:]  (w==0 exactly on masked; skip is exact)
    {
        float av[8];
#pragma unroll
        for (int i = 0; i < 8; i++) av[i] = 0.f;
        const float* eb = g_enc + (size_t)b * Sz * Hz + ht;
        int ii = 0;
        for (; ii + 8 <= n_half; ii += 8) {
#pragma unroll
            for (int i = 0; i < 8; i++) {
                int s = s_list[half][ii + i];
                av[i] = fmaf(s_w[half][s], eb[(size_t)s * Hz], av[i]);
            }
        }
        for (; ii < n_half; ii++) {
            int s = s_list[half][ii];
            av[ii & 7] = fmaf(s_w[half][s], eb[(size_t)s * Hz], av[ii & 7]);
        }
        s_q[half][ht] = ((av[0] + av[1]) + (av[2] + av[3])) + ((av[4] + av[5]) + (av[6] + av[7]));
    }
    __syncthreads();
    // qq2 = q @ pWq^T + pbq (warp-cooperative)
    for (int row = wd; row < Hz; row += 16) {
        const float4* wr = (const float4*)(pWq + (size_t)row * Hz);
        float4 w1 = wr[ln], w2 = wr[32 + ln];
        float4 ha = *(const float4*)&s_q[0][ln << 2];
        float4 hb = *(const float4*)&s_q[0][128 + (ln << 2)];
        float4 hc = *(const float4*)&s_q[1][ln << 2];
        float4 hd = *(const float4*)&s_q[1][128 + (ln << 2)];
        float a0 = 0.f, a1 = 0.f;
        a0 = fmaf(w1.x, ha.x, a0); a0 = fmaf(w1.y, ha.y, a0);
        a0 = fmaf(w1.z, ha.z, a0); a0 = fmaf(w1.w, ha.w, a0);
        a0 = fmaf(w2.x, hb.x, a0); a0 = fmaf(w2.y, hb.y, a0);
        a0 = fmaf(w2.z, hb.z, a0); a0 = fmaf(w2.w, hb.w, a0);
        a1 = fmaf(w1.x, hc.x, a1); a1 = fmaf(w1.y, hc.y, a1);
        a1 = fmaf(w1.z, hc.z, a1); a1 = fmaf(w1.w, hc.w, a1);
        a1 = fmaf(w2.x, hd.x, a1); a1 = fmaf(w2.y, hd.y, a1);
        a1 = fmaf(w2.z, hd.z, a1); a1 = fmaf(w2.w, hd.w, a1);
        wredd(a0, a1);
        if (!ln) {
            float bq = pbq[row];
            s_qq[0][row] = a0 + bq;
            s_qq[1][row] = a1 + bq;
        }
    }
    __syncthreads();
    // pointer logits over compact lists (masked stay -inf from init)
    for (int ii = wd; ii < nmax; ii += 16) {
        int s0 = (ii < n0) ? s_list[0][ii] : -1;
        int s1 = (ii < n1) ? s_list[1][ii] : -1;
        float a0 = 0.f, a1 = 0.f;
        if (s0 >= 0) {
            const float4* rp = (const float4*)(g_refp + ((size_t)b0 * Sz + s0) * Hz);
#pragma unroll
            for (int i = 0; i < 2; i++) {
                int c = i * 32 + ln;
                float4 rv = rp[c];
                float4 qv = *(const float4*)&s_qq[0][c << 2];
                float4 vv = *(const float4*)&s_Vp[c << 2];
                a0 = fmaf(vv.x, xtanh(qv.x + rv.x), a0);
                a0 = fmaf(vv.y, xtanh(qv.y + rv.y), a0);
                a0 = fmaf(vv.z, xtanh(qv.z + rv.z), a0);
                a0 = fmaf(vv.w, xtanh(qv.w + rv.w), a0);
            }
        }
        if (s1 >= 0) {
            const float4* rp = (const float4*)(g_refp + ((size_t)b1 * Sz + s1) * Hz);
#pragma unroll
            for (int i = 0; i < 2; i++) {
                int c = i * 32 + ln;
                float4 rv = rp[c];
                float4 qv = *(const float4*)&s_qq[1][c << 2];
                float4 vv = *(const float4*)&s_Vp[c << 2];
                a1 = fmaf(vv.x, xtanh(qv.x + rv.x), a1);
                a1 = fmaf(vv.y, xtanh(qv.y + rv.y), a1);
                a1 = fmaf(vv.z, xtanh(qv.z + rv.z), a1);
                a1 = fmaf(vv.w, xtanh(qv.w + rv.w), a1);
            }
        }
        wredd(a0, a1);
        if (!ln) {
            if (s0 >= 0) s_lg[0][s0] = C_EXPLORE * xtanh(a0);
            if (s1 >= 0) s_lg[1][s1] = C_EXPLORE * xtanh(a1);
        }
    }
    __syncthreads();
    // softmax -> probs; gumbel argmax -> idx
    {
        float v = (ht < Sz) ? s_lg[half][ht] : -INFINITY;
        s_red[half][ht] = v; __syncthreads();
#pragma unroll
        for (int o = 128; o; o >>= 1) { if (ht < o) s_red[half][ht] = fmaxf(s_red[half][ht], s_red[half][ht + o]); __syncthreads(); }
        float m = s_red[half][0]; __syncthreads();
        float e = (ht < Sz) ? expf(v - m) : 0.f;
        s_red[half][ht] = e; __syncthreads();
#pragma unroll
        for (int o = 128; o; o >>= 1) { if (ht < o) s_red[half][ht] += s_red[half][ht + o]; __syncthreads(); }
        float sm = s_red[half][0]; __syncthreads();
        if (ht < Sz)
            out_probs[(size_t)b * Sz + ht] = e / sm;
        float pv = -INFINITY;
        if (ht < Sz) {
            unsigned key0, key1;
#if PARTITIONABLE
            tf2x32(0u, 1u, 0u, (unsigned)t, key0, key1);
#else
            {
                unsigned a0k, b0k;
                unsigned idx0 = 2u * t, idx1 = 2u * t + 1u;
                if (idx0 < Sz) { tf2x32(0u, 1u, idx0, idx0 + Sz, a0k, b0k); key0 = a0k; }
                else           { tf2x32(0u, 1u, idx0 - Sz, idx0, a0k, b0k); key0 = b0k; }
                if (idx1 < Sz) { tf2x32(0u, 1u, idx1, idx1 + Sz, a0k, b0k); key1 = a0k; }
                else           { tf2x32(0u, 1u, idx1 - Sz, idx1, a0k, b0k); key1 = b0k; }
            }
#endif
            unsigned m0 = (unsigned)(b * Sz + ht);
            unsigned ra, rb, bits;
#if PARTITIONABLE
            tf2x32(key0, key1, 0u, m0, ra, rb);
            bits = ra ^ rb;
#else
            const unsigned halfn = (Bz * Sz) / 2;
            if (m0 < halfn) { tf2x32(key0, key1, m0, m0 + halfn, ra, rb); bits = ra; }
            else            { tf2x32(key0, key1, m0 - halfn, m0, ra, rb); bits = rb; }
#endif
            float f = __uint_as_float((bits >> 9) | 0x3f800000u) - 1.0f;
            float u = fmaxf(f, 1.17549435e-38f);
            pv = v - logf(-logf(u));
        }
        s_red[half][ht] = pv; s_ridx[half][ht] = ht; __syncthreads();
#pragma unroll
        for (int o = 128; o; o >>= 1) {
            if (ht < o) {
                float a2 = s_red[half][ht], c2 = s_red[half][ht + o];
                int ia = s_ridx[half][ht], ic = s_ridx[half][ht + o];
                if (c2 > a2 || (c2 == a2 && ic < ia)) { s_red[half][ht] = c2; s_ridx[half][ht] = ic; }
            }
            __syncthreads();
        }
        if (!ht) {
            int id = s_ridx[half][0];
            g_idx[b] = id;
            out_idx[b] = (float)id;
        }
    }
}

// ---------------- host ----------------
template <typename T>
static T* symaddr(const void* sym) {
    void* p = nullptr;
    cudaGetSymbolAddress(&p, sym);
    return (T*)p;
}

extern "C" void kernel_launch(void* const* d_in, const int* in_sizes, int n_in,
                              void* d_out, int out_size) {
    const float* in_inputs = (const float*)d_in[0];
    const float* in_emb    = (const float*)d_in[1];
    const float* in_eWih   = (const float*)d_in[2];
    const float* in_eWhh   = (const float*)d_in[3];
    const float* in_ebih   = (const float*)d_in[4];
    const float* in_ebhh   = (const float*)d_in[5];
    const float* in_dWih   = (const float*)d_in[6];
    const float* in_dWhh   = (const float*)d_in[7];
    const float* in_dbih   = (const float*)d_in[8];
    const float* in_dbhh   = (const float*)d_in[9];
    const float* in_gWq    = (const float*)d_in[10];
    const float* in_gbq    = (const float*)d_in[11];
    const float* in_gWr    = (const float*)d_in[12];
    const float* in_gbr    = (const float*)d_in[13];
    const float* in_gV     = (const float*)d_in[14];
    const float* in_pWq    = (const float*)d_in[15];
    const float* in_pbq    = (const float*)d_in[16];
    const float* in_pWr    = (const float*)d_in[17];
    const float* in_pbr    = (const float*)d_in[18];
    const float* in_pV     = (const float*)d_in[19];
    const float* in_start  = (const float*)d_in[20];
    float* out = (float*)d_out;

    float* p_h0 = symaddr<float>(g_h0);
    float* p_h1 = symaddr<float>(g_h1);

    k_init<<<512, 256>>>();
    k_prep<<<4, 256>>>(in_emb, in_eWih, in_dWih, in_start);

    for (int t = 0; t < Sz; t++) {
        const float* rh = (t & 1) ? p_h1 : p_h0;
        float* wh       = (t & 1) ? p_h0 : p_h1;
        k_lstm_step<<<128, 256>>>(rh, wh, in_eWhh, in_ebih, in_ebhh, in_inputs, t, 0);
    }

    {
        dim3 grid(Hz / 64, (Bz * Sz) / 64, 2);
        k_ref<<<grid, 256>>>(in_gWr, in_gbr, in_pWr, in_pbr);
    }

    float* out_probs = out;
    float* out_idx = out + (size_t)Sz * Bz * Sz;
    for (int t = 0; t < Sz; t++) {
        const float* rh = (t & 1) ? p_h1 : p_h0;
        float* wh       = (t & 1) ? p_h0 : p_h1;
        k_lstm_step<<<128, 256>>>(rh, wh, in_dWhh, in_dbih, in_dbhh, in_inputs, t, 1);
        k_dec_attn<<<Bz / 2, 512>>>(wh, in_gWq, in_gbq, in_gV, in_pWq, in_pbq, in_pV,
                                    out_probs + (size_t)t * Bz * Sz,
                                    out_idx + (size_t)t * Bz, t);
    }
    (void)in_sizes; (void)n_in; (void)out_size;
}

// round 11
// speedup vs baseline: 1.3372x; 1.0005x over previous
#include <cuda_runtime.h>
#include <cuda_bf16.h>
#include <math.h>
#include <stdint.h>

#define Bz 512
#define Sz 100
#define Ez 256
#define Hz 256
#define G4 1024
#define C_EXPLORE 10.0f
#define PARTITIONABLE 1

typedef unsigned long long u64;

// ---------------- packed f32x2 helpers (sm_100+) ----------------
__device__ __forceinline__ u64 pk2(float lo, float hi) {
    u64 d; asm("mov.b64 %0, {%1, %2};" : "=l"(d) : "f"(lo), "f"(hi)); return d;
}
__device__ __forceinline__ void upk2(u64 v, float& lo, float& hi) {
    asm("mov.b64 {%0, %1}, %2;" : "=f"(lo), "=f"(hi) : "l"(v));
}
__device__ __forceinline__ u64 fma2(u64 a, u64 b, u64 c) {
    u64 d; asm("fma.rn.f32x2 %0, %1, %2, %3;" : "=l"(d) : "l"(a), "l"(b), "l"(c)); return d;
}

// ---------------- fast exact-enough tanh (Eigen/XLA rational + rcp NR) ----------------
__device__ __forceinline__ float xtanh(float x) {
    const float c = 7.90531110763549805f;
    float cx = fminf(fmaxf(x, -c), c);
    float r = cx * cx;
    float p = -2.76076847742355e-16f;
    p = fmaf(p, r, 2.00018790482477e-13f);
    p = fmaf(p, r, -8.60467152213735e-11f);
    p = fmaf(p, r, 5.12229709037114e-08f);
    p = fmaf(p, r, 1.48572235717979e-05f);
    p = fmaf(p, r, 6.37261928875436e-04f);
    p = fmaf(p, r, 4.89352455891786e-03f);
    float num = cx * p;
    float q = 1.19825839466702e-06f;
    q = fmaf(q, r, 1.18534705686654e-04f);
    q = fmaf(q, r, 2.26843463243900e-03f);
    q = fmaf(q, r, 4.89352518554385e-03f);
    float ri;
    asm("rcp.approx.f32 %0, %1;" : "=f"(ri) : "f"(q));
    ri = ri * fmaf(-q, ri, 2.0f);
    return num * ri;
}
__device__ __forceinline__ float sigf(float x) {
    return 0.5f + 0.5f * xtanh(0.5f * x);
}

// ---------------- device state ----------------
__device__ float g_h0[Bz * Hz];
__device__ float g_h1[Bz * Hz];
__device__ float g_c[Bz * Hz];
__device__ float g_enc[(size_t)Bz * Sz * Hz];
__device__ float g_refg[(size_t)Bz * Sz * Hz];
__device__ float g_refp[(size_t)Bz * Sz * Hz];
__device__ float g_Penc[2 * G4];
__device__ float g_Pdec[2 * G4];
__device__ float g_startproj[G4];
__device__ int g_idx[Bz];
__device__ unsigned char g_mask[Bz * Sz];

// ---------------- threefry2x32 ----------------
__device__ __forceinline__ unsigned rotl32(unsigned v, int r) {
    return (v << r) | (v >> (32 - r));
}
__device__ __forceinline__ void tf2x32(unsigned k0, unsigned k1,
                                       unsigned x0, unsigned x1,
                                       unsigned& o0, unsigned& o1) {
    unsigned ks2 = 0x1BD11BDAu ^ k0 ^ k1;
    x0 += k0; x1 += k1;
#define TF_G(a,b,c,d) \
    x0 += x1; x1 = rotl32(x1,a); x1 ^= x0; \
    x0 += x1; x1 = rotl32(x1,b); x1 ^= x0; \
    x0 += x1; x1 = rotl32(x1,c); x1 ^= x0; \
    x0 += x1; x1 = rotl32(x1,d); x1 ^= x0;
    TF_G(13,15,26,6);  x0 += k1;  x1 += ks2 + 1u;
    TF_G(17,29,16,24); x0 += ks2; x1 += k0 + 2u;
    TF_G(13,15,26,6);  x0 += k0;  x1 += k1 + 3u;
    TF_G(17,29,16,24); x0 += k1;  x1 += ks2 + 4u;
    TF_G(13,15,26,6);  x0 += ks2; x1 += k0 + 5u;
#undef TF_G
    o0 = x0; o1 = x1;
}

// ---------------- setup ----------------
__global__ void k_init() {
    int i = blockIdx.x * blockDim.x + threadIdx.x;
    if (i < Bz * Hz) { g_h0[i] = 0.f; g_c[i] = 0.f; }
    if (i < Bz * Sz) g_mask[i] = 0;
    if (i < Bz) g_idx[i] = 0;
}

__global__ void k_prep(const float* __restrict__ emb,
                       const float* __restrict__ eWih,
                       const float* __restrict__ dWih,
                       const float* __restrict__ start) {
    int j = blockIdx.x * 256 + threadIdx.x;
    if (j >= G4) return;
    float pe0 = 0.f, pe1 = 0.f, pd0 = 0.f, pd1 = 0.f, sp = 0.f;
    for (int e = 0; e < Ez; e++) {
        float we = eWih[j * Ez + e], wd = dWih[j * Ez + e];
        pe0 = fmaf(emb[e], we, pe0);
        pe1 = fmaf(emb[Ez + e], we, pe1);
        pd0 = fmaf(emb[e], wd, pd0);
        pd1 = fmaf(emb[Ez + e], wd, pd1);
        sp  = fmaf(start[e], wd, sp);
    }
    g_Penc[j] = pe0; g_Penc[G4 + j] = pe1;
    g_Pdec[j] = pd0; g_Pdec[G4 + j] = pd1;
    g_startproj[j] = sp;
}

// ---------------- fused gates GEMM + LSTM cell: 128 blocks x 512 thr, 32b x 32j ----------------
// Same per-block W traffic as the 19.5us version, but 16 warps/SM for latency hiding.
__global__ void __launch_bounds__(512) k_lstm_step(const float* __restrict__ rh,
                                                   float* __restrict__ wh,
                                                   const float* __restrict__ W,
                                                   const float* __restrict__ bih,
                                                   const float* __restrict__ bhh,
                                                   const float* __restrict__ inp,
                                                   int t, int is_dec) {
    __shared__ float sA[2][32 * 36];
    __shared__ float2 sW01[2][32 * 33];
    __shared__ float2 sW23[2][32 * 33];
    const int tid = threadIdx.x, bid = blockIdx.x;
    const int tx = tid & 31, ty = tid >> 5;          // ty 0..15, 2 rows each
    const int bm = (bid >> 3) * 32, jn = (bid & 7) * 32;
    const int j = jn + tx;
    const int htid = tid & 255;
    const int lrow = htid >> 3;          // 0..31
    const int lk = (htid & 7) << 2;      // 0,4,..,28
    const int hid = tid >> 8;            // 0: gates 0,1 ; 1: gates 2,3
    const bool aload = tid < 256;

    const float* Ab  = rh + (size_t)(bm + lrow) * Hz + lk;
    const float* WbA = W + (size_t)((hid << 9) + jn + lrow) * Hz + lk;   // gate 2*hid
    const float* WbB = WbA + (size_t)256 * Hz;                            // gate 2*hid+1

    float4 pa  = aload ? *(const float4*)Ab : make_float4(0.f, 0.f, 0.f, 0.f);
    float4 pwA = *(const float4*)WbA;
    float4 pwB = *(const float4*)WbB;

    u64 acc2[2][2];   // [row r][gate pair]
    acc2[0][0] = pk2(0.f, 0.f); acc2[0][1] = acc2[0][0];
    acc2[1][0] = acc2[0][0];    acc2[1][1] = acc2[0][0];

    for (int k0 = 0; k0 < Hz; k0 += 32) {
        const int buf = (k0 >> 5) & 1;
        float* a_s = sA[buf];
        float2* wp = hid ? sW23[buf] : sW01[buf];
        if (aload) {
            a_s[(lk + 0) * 36 + lrow] = pa.x;
            a_s[(lk + 1) * 36 + lrow] = pa.y;
            a_s[(lk + 2) * 36 + lrow] = pa.z;
            a_s[(lk + 3) * 36 + lrow] = pa.w;
        }
        {
            const float* pA = (const float*)&pwA;
            const float* pB = (const float*)&pwB;
#pragma unroll
            for (int i = 0; i < 4; i++)
                wp[(lk + i) * 33 + lrow] = make_float2(pA[i], pB[i]);
        }
        __syncthreads();
        if (k0 + 32 < Hz) {
            if (aload) pa = *(const float4*)(Ab + k0 + 32);
            pwA = *(const float4*)(WbA + k0 + 32);
            pwB = *(const float4*)(WbB + k0 + 32);
        }
        float2* w01b = sW01[buf];
        float2* w23b = sW23[buf];
#pragma unroll 8
        for (int k = 0; k < 32; k++) {
            float2 a2 = *(const float2*)&a_s[k * 36 + (ty << 1)];   // broadcast
            u64 wp01 = *(const u64*)&w01b[k * 33 + tx];
            u64 wp23 = *(const u64*)&w23b[k * 33 + tx];
            u64 ax = pk2(a2.x, a2.x);
            u64 ay = pk2(a2.y, a2.y);
            acc2[0][0] = fma2(wp01, ax, acc2[0][0]);
            acc2[0][1] = fma2(wp23, ax, acc2[0][1]);
            acc2[1][0] = fma2(wp01, ay, acc2[1][0]);
            acc2[1][1] = fma2(wp23, ay, acc2[1][1]);
        }
        __syncthreads();
    }

    const float* P = is_dec ? g_Pdec : g_Penc;
    float xb[4], pb0[4], pb1[4];
#pragma unroll
    for (int g = 0; g < 4; g++) {
        pb0[g] = P[(g << 8) + j];
        pb1[g] = P[G4 + (g << 8) + j];
        xb[g]  = bih[(g << 8) + j] + bhh[(g << 8) + j];
    }
#pragma unroll
    for (int r = 0; r < 2; r++) {
        int b = bm + (ty << 1) + r;
        float a0, a1, a2, a3;
        upk2(acc2[r][0], a0, a1);
        upk2(acc2[r][1], a2, a3);
        float xg[4];
        if (is_dec && t == 0) {
#pragma unroll
            for (int g = 0; g < 4; g++) xg[g] = g_startproj[(g << 8) + j];
        } else {
            int s = is_dec ? g_idx[b] : t;
            float c0 = inp[(b * 2) * Sz + s];
            float c1 = inp[(b * 2 + 1) * Sz + s];
#pragma unroll
            for (int g = 0; g < 4; g++) xg[g] = fmaf(c0, pb0[g], c1 * pb1[g]);
        }
        float gi = a0 + xg[0] + xb[0];
        float gf = a1 + xg[1] + xb[1];
        float gc = a2 + xg[2] + xb[2];
        float go = a3 + xg[3] + xb[3];
        float cc = sigf(gf) * g_c[b * Hz + j] + sigf(gi) * xtanh(gc);
        g_c[b * Hz + j] = cc;
        float hh = sigf(go) * xtanh(cc);
        wh[b * Hz + j] = hh;
        if (!is_dec) g_enc[(size_t)(b * Sz + t) * Hz + j] = hh;
    }
}

// ---------------- ref projections (z=0: glimpse, z=1: pointer) ----------------
__global__ void __launch_bounds__(256) k_ref(const float* __restrict__ gWr,
                                             const float* __restrict__ gbr,
                                             const float* __restrict__ pWr,
                                             const float* __restrict__ pbr) {
    __shared__ float As[16][64];
    __shared__ float Ws[16][64];
    const float* A = g_enc;
    const float* W = blockIdx.z ? pWr : gWr;
    const float* bias = blockIdx.z ? pbr : gbr;
    float* C = blockIdx.z ? g_refp : g_refg;
    const int K = Hz, N = Hz;
    const int bm = blockIdx.y * 64;
    const int bn = blockIdx.x * 64;
    const int t = threadIdx.x;
    const int tx = t & 15, ty = t >> 4;
    const int lr = t >> 2, lc = (t & 3) << 2;
    float acc[4][4];
#pragma unroll
    for (int i = 0; i < 4; i++)
#pragma unroll
        for (int jj = 0; jj < 4; jj++) acc[i][jj] = 0.f;
    const float* Ab = A + (size_t)(bm + lr) * K + lc;
    const float* Wb = W + (size_t)(bn + lr) * K + lc;
    for (int k0 = 0; k0 < K; k0 += 16) {
        float4 av = *(const float4*)(Ab + k0);
        float4 wv = *(const float4*)(Wb + k0);
        As[lc + 0][lr] = av.x; As[lc + 1][lr] = av.y;
        As[lc + 2][lr] = av.z; As[lc + 3][lr] = av.w;
        Ws[lc + 0][lr] = wv.x; Ws[lc + 1][lr] = wv.y;
        Ws[lc + 2][lr] = wv.z; Ws[lc + 3][lr] = wv.w;
        __syncthreads();
#pragma unroll
        for (int k = 0; k < 16; k++) {
            float4 a4 = *(const float4*)&As[k][ty << 2];
            float4 w4 = *(const float4*)&Ws[k][tx << 2];
            float am[4] = {a4.x, a4.y, a4.z, a4.w};
            float wn[4] = {w4.x, w4.y, w4.z, w4.w};
#pragma unroll
            for (int i = 0; i < 4; i++)
#pragma unroll
                for (int jj = 0; jj < 4; jj++)
                    acc[i][jj] = fmaf(am[i], wn[jj], acc[i][jj]);
        }
        __syncthreads();
    }
#pragma unroll
    for (int i = 0; i < 4; i++) {
        int m = bm + (ty << 2) + i;
#pragma unroll
        for (int jj = 0; jj < 4; jj++) {
            int n = bn + (tx << 2) + jj;
            C[(size_t)m * N + n] = acc[i][jj] + bias[n];
        }
    }
}

// warp 4-way reduce
__device__ __forceinline__ void wredd4(float& a0, float& a1, float& a2, float& a3) {
#pragma unroll
    for (int o = 16; o; o >>= 1) {
        a0 += __shfl_xor_sync(0xffffffffu, a0, o);
        a1 += __shfl_xor_sync(0xffffffffu, a1, o);
        a2 += __shfl_xor_sync(0xffffffffu, a2, o);
        a3 += __shfl_xor_sync(0xffffffffu, a3, o);
    }
}

// ---------------- fused decoder attention + sample: FOUR b per block, 1024 thr ----------------
__global__ void __launch_bounds__(1024) k_dec_attn(const float* __restrict__ h,
                                                   const float* __restrict__ gWq,
                                                   const float* __restrict__ gbq,
                                                   const float* __restrict__ gV,
                                                   const float* __restrict__ pWq,
                                                   const float* __restrict__ pbq,
                                                   const float* __restrict__ pV,
                                                   float* __restrict__ out_probs,
                                                   float* __restrict__ out_idx,
                                                   int t) {
    __shared__ __align__(16) float s_h[4][Hz];
    __shared__ __align__(16) float s_qq[4][Hz];
    __shared__ __align__(16) float s_q[4][Hz];
    __shared__ __align__(16) float s_Vg[Hz];
    __shared__ __align__(16) float s_Vp[Hz];
    __shared__ float s_lg[4][128];
    __shared__ float s_w[4][128];
    __shared__ float s_red[4][256];
    __shared__ int s_ridx[4][256];
    __shared__ unsigned char s_m[4][104];
    __shared__ short s_list[4][104];
    __shared__ int s_ccnt[4][4];

    const int tid = threadIdx.x;
    const int qt = tid >> 8;            // quarter 0..3
    const int ht = tid & 255;
    const int b = (blockIdx.x << 2) + qt;
    const int bb = blockIdx.x << 2;
    const int wd = tid >> 5;            // 0..31
    const int ln = tid & 31;

    if (t > 0 && ht == 0) g_mask[b * Sz + g_idx[b]] = 1;
    __syncthreads();
    if (ht < Sz) s_m[qt][ht] = g_mask[b * Sz + ht];
    s_h[qt][ht] = h[b * Hz + ht];
    if (tid < Hz) s_Vg[tid] = gV[tid];
    else if (tid < 2 * Hz) s_Vp[tid - Hz] = pV[tid - Hz];
    __syncthreads();

    // ---- deterministic compaction of unmasked s (ascending, per quarter) ----
    bool un = false; int pre = 0, chunk = 0;
    if (ht < 128) {
        chunk = ht >> 5;
        un = (ht < Sz) && !s_m[qt][ht];
        unsigned bal = __ballot_sync(0xffffffffu, un);
        pre = __popc(bal & ((1u << (ht & 31)) - 1));
        if ((ht & 31) == 0) s_ccnt[qt][chunk] = __popc(bal);
    }
    __syncthreads();
    int nq[4];
#pragma unroll
    for (int g = 0; g < 4; g++)
        nq[g] = s_ccnt[g][0] + s_ccnt[g][1] + s_ccnt[g][2] + s_ccnt[g][3];
    const int n_self = nq[qt];
    int nmax = nq[0];
#pragma unroll
    for (int g = 1; g < 4; g++) nmax = nq[g] > nmax ? nq[g] : nmax;
    if (un) {
        int base = 0;
        for (int i = 0; i < chunk; i++) base += s_ccnt[qt][i];
        s_list[qt][base + pre] = (short)ht;
    }
    if (ht < 128) s_lg[qt][ht] = -INFINITY;
    __syncthreads();

    // qq = h @ gWq^T + gbq, warp-cooperative rows for ALL 4 b's (W read once/block)
    for (int row = wd; row < Hz; row += 32) {
        const float4* wr = (const float4*)(gWq + (size_t)row * Hz);
        float4 w1 = wr[ln], w2 = wr[32 + ln];
        float a[4];
#pragma unroll
        for (int g = 0; g < 4; g++) {
            float4 ha = *(const float4*)&s_h[g][ln << 2];
            float4 hb = *(const float4*)&s_h[g][128 + (ln << 2)];
            float ag = 0.f;
            ag = fmaf(w1.x, ha.x, ag); ag = fmaf(w1.y, ha.y, ag);
            ag = fmaf(w1.z, ha.z, ag); ag = fmaf(w1.w, ha.w, ag);
            ag = fmaf(w2.x, hb.x, ag); ag = fmaf(w2.y, hb.y, ag);
            ag = fmaf(w2.z, hb.z, ag); ag = fmaf(w2.w, hb.w, ag);
            a[g] = ag;
        }
        wredd4(a[0], a[1], a[2], a[3]);
        if (!ln) {
            float bq = gbq[row];
#pragma unroll
            for (int g = 0; g < 4; g++) s_qq[g][row] = a[g] + bq;
        }
    }
    __syncthreads();
    // glimpse logits over compact lists (warp handles one slot for all 4 b's)
    for (int ii = wd; ii < nmax; ii += 32) {
        int sg[4]; float a[4];
#pragma unroll
        for (int g = 0; g < 4; g++) {
            sg[g] = (ii < nq[g]) ? s_list[g][ii] : -1;
            a[g] = 0.f;
        }
#pragma unroll
        for (int g = 0; g < 4; g++) {
            if (sg[g] >= 0) {
                const float4* rg = (const float4*)(g_refg + ((size_t)(bb + g) * Sz + sg[g]) * Hz);
#pragma unroll
                for (int i = 0; i < 2; i++) {
                    int c = i * 32 + ln;
                    float4 rv = rg[c];
                    float4 qv = *(const float4*)&s_qq[g][c << 2];
                    float4 vv = *(const float4*)&s_Vg[c << 2];
                    a[g] = fmaf(vv.x, xtanh(qv.x + rv.x), a[g]);
                    a[g] = fmaf(vv.y, xtanh(qv.y + rv.y), a[g]);
                    a[g] = fmaf(vv.z, xtanh(qv.z + rv.z), a[g]);
                    a[g] = fmaf(vv.w, xtanh(qv.w + rv.w), a[g]);
                }
            }
        }
        wredd4(a[0], a[1], a[2], a[3]);
        if (!ln) {
#pragma unroll
            for (int g = 0; g < 4; g++)
                if (sg[g] >= 0) s_lg[g][sg[g]] = a[g];
        }
    }
    __syncthreads();
    // softmax -> s_w (per quarter, 256 threads)
    {
        float v = (ht < Sz) ? s_lg[qt][ht] : -INFINITY;
        s_red[qt][ht] = v; __syncthreads();
#pragma unroll
        for (int o = 128; o; o >>= 1) { if (ht < o) s_red[qt][ht] = fmaxf(s_red[qt][ht], s_red[qt][ht + o]); __syncthreads(); }
        float m = s_red[qt][0]; __syncthreads();
        float e = (ht < Sz) ? expf(v - m) : 0.f;
        s_red[qt][ht] = e; __syncthreads();
#pragma unroll
        for (int o = 128; o; o >>= 1) { if (ht < o) s_red[qt][ht] += s_red[qt][ht + o]; __syncthreads(); }
        float sm = s_red[qt][0]; __syncthreads();
        if (ht < 128) s_w[qt][ht] = (ht < Sz) ? e / sm : 0.f;
    }
    __syncthreads();
    // q = sum over unmasked s of w[s]*enc[b,s,:] (w==0 exactly on masked; skip exact)
    {
        float av[8];
#pragma unroll
        for (int i = 0; i < 8; i++) av[i] = 0.f;
        const float* eb = g_enc + (size_t)b * Sz * Hz + ht;
        int ii = 0;
        for (; ii + 8 <= n_self; ii += 8) {
#pragma unroll
            for (int i = 0; i < 8; i++) {
                int s = s_list[qt][ii + i];
                av[i] = fmaf(s_w[qt][s], eb[(size_t)s * Hz], av[i]);
            }
        }
        for (; ii < n_self; ii++) {
            int s = s_list[qt][ii];
            av[ii & 7] = fmaf(s_w[qt][s], eb[(size_t)s * Hz], av[ii & 7]);
        }
        s_q[qt][ht] = ((av[0] + av[1]) + (av[2] + av[3])) + ((av[4] + av[5]) + (av[6] + av[7]));
    }
    __syncthreads();
    // qq2 = q @ pWq^T + pbq (warp-cooperative, all 4 b's)
    for (int row = wd; row < Hz; row += 32) {
        const float4* wr = (const float4*)(pWq + (size_t)row * Hz);
        float4 w1 = wr[ln], w2 = wr[32 + ln];
        float a[4];
#pragma unroll
        for (int g = 0; g < 4; g++) {
            float4 ha = *(const float4*)&s_q[g][ln << 2];
            float4 hb = *(const float4*)&s_q[g][128 + (ln << 2)];
            float ag = 0.f;
            ag = fmaf(w1.x, ha.x, ag); ag = fmaf(w1.y, ha.y, ag);
            ag = fmaf(w1.z, ha.z, ag); ag = fmaf(w1.w, ha.w, ag);
            ag = fmaf(w2.x, hb.x, ag); ag = fmaf(w2.y, hb.y, ag);
            ag = fmaf(w2.z, hb.z, ag); ag = fmaf(w2.w, hb.w, ag);
            a[g] = ag;
        }
        wredd4(a[0], a[1], a[2], a[3]);
        if (!ln) {
            float bq = pbq[row];
#pragma unroll
            for (int g = 0; g < 4; g++) s_qq[g][row] = a[g] + bq;
        }
    }
    __syncthreads();
    // pointer logits over compact lists (masked stay -inf from init)
    for (int ii = wd; ii < nmax; ii += 32) {
        int sg[4]; float a[4];
#pragma unroll
        for (int g = 0; g < 4; g++) {
            sg[g] = (ii < nq[g]) ? s_list[g][ii] : -1;
            a[g] = 0.f;
        }
#pragma unroll
        for (int g = 0; g < 4; g++) {
            if (sg[g] >= 0) {
                const float4* rp = (const float4*)(g_refp + ((size_t)(bb + g) * Sz + sg[g]) * Hz);
#pragma unroll
                for (int i = 0; i < 2; i++) {
                    int c = i * 32 + ln;
                    float4 rv = rp[c];
                    float4 qv = *(const float4*)&s_qq[g][c << 2];
                    float4 vv = *(const float4*)&s_Vp[c << 2];
                    a[g] = fmaf(vv.x, xtanh(qv.x + rv.x), a[g]);
                    a[g] = fmaf(vv.y, xtanh(qv.y + rv.y), a[g]);
                    a[g] = fmaf(vv.z, xtanh(qv.z + rv.z), a[g]);
                    a[g] = fmaf(vv.w, xtanh(qv.w + rv.w), a[g]);
                }
            }
        }
        wredd4(a[0], a[1], a[2], a[3]);
        if (!ln) {
#pragma unroll
            for (int g = 0; g < 4; g++)
                if (sg[g] >= 0) s_lg[g][sg[g]] = C_EXPLORE * xtanh(a[g]);
        }
    }
    __syncthreads();
    // softmax -> probs; gumbel argmax -> idx (per quarter)
    {
        float v = (ht < Sz) ? s_lg[qt][ht] : -INFINITY;
        s_red[qt][ht] = v; __syncthreads();
#pragma unroll
        for (int o = 128; o; o >>= 1) { if (ht < o) s_red[qt][ht] = fmaxf(s_red[qt][ht], s_red[qt][ht + o]); __syncthreads(); }
        float m = s_red[qt][0]; __syncthreads();
        float e = (ht < Sz) ? expf(v - m) : 0.f;
        s_red[qt][ht] = e; __syncthreads();
#pragma unroll
        for (int o = 128; o; o >>= 1) { if (ht < o) s_red[qt][ht] += s_red[qt][ht + o]; __syncthreads(); }
        float sm = s_red[qt][0]; __syncthreads();
        if (ht < Sz)
            out_probs[(size_t)b * Sz + ht] = e / sm;
        float pv = -INFINITY;
        if (ht < Sz) {
            unsigned key0, key1;
#if PARTITIONABLE
            tf2x32(0u, 1u, 0u, (unsigned)t, key0, key1);
#else
            {
                unsigned a0k, b0k;
                unsigned idx0 = 2u * t, idx1 = 2u * t + 1u;
                if (idx0 < Sz) { tf2x32(0u, 1u, idx0, idx0 + Sz, a0k, b0k); key0 = a0k; }
                else           { tf2x32(0u, 1u, idx0 - Sz, idx0, a0k, b0k); key0 = b0k; }
                if (idx1 < Sz) { tf2x32(0u, 1u, idx1, idx1 + Sz, a0k, b0k); key1 = a0k; }
                else           { tf2x32(0u, 1u, idx1 - Sz, idx1, a0k, b0k); key1 = b0k; }
            }
#endif
            unsigned m0 = (unsigned)(b * Sz + ht);
            unsigned ra, rb, bits;
#if PARTITIONABLE
            tf2x32(key0, key1, 0u, m0, ra, rb);
            bits = ra ^ rb;
#else
            const unsigned halfn = (Bz * Sz) / 2;
            if (m0 < halfn) { tf2x32(key0, key1, m0, m0 + halfn, ra, rb); bits = ra; }
            else            { tf2x32(key0, key1, m0 - halfn, m0, ra, rb); bits = rb; }
#endif
            float f = __uint_as_float((bits >> 9) | 0x3f800000u) - 1.0f;
            float u = fmaxf(f, 1.17549435e-38f);
            pv = v - logf(-logf(u));
        }
        s_red[qt][ht] = pv; s_ridx[qt][ht] = ht; __syncthreads();
#pragma unroll
        for (int o = 128; o; o >>= 1) {
            if (ht < o) {
                float a2 = s_red[qt][ht], c2 = s_red[qt][ht + o];
                int ia = s_ridx[qt][ht], ic = s_ridx[qt][ht + o];
                if (c2 > a2 || (c2 == a2 && ic < ia)) { s_red[qt][ht] = c2; s_ridx[qt][ht] = ic; }
            }
            __syncthreads();
        }
        if (!ht) {
            int id = s_ridx[qt][0];
            g_idx[b] = id;
            out_idx[b] = (float)id;
        }
    }
}

// ---------------- host ----------------
template <typename T>
static T* symaddr(const void* sym) {
    void* p = nullptr;
    cudaGetSymbolAddress(&p, sym);
    return (T*)p;
}

extern "C" void kernel_launch(void* const* d_in, const int* in_sizes, int n_in,
                              void* d_out, int out_size) {
    const float* in_inputs = (const float*)d_in[0];
    const float* in_emb    = (const float*)d_in[1];
    const float* in_eWih   = (const float*)d_in[2];
    const float* in_eWhh   = (const float*)d_in[3];
    const float* in_ebih   = (const float*)d_in[4];
    const float* in_ebhh   = (const float*)d_in[5];
    const float* in_dWih   = (const float*)d_in[6];
    const float* in_dWhh   = (const float*)d_in[7];
    const float* in_dbih   = (const float*)d_in[8];
    const float* in_dbhh   = (const float*)d_in[9];
    const float* in_gWq    = (const float*)d_in[10];
    const float* in_gbq    = (const float*)d_in[11];
    const float* in_gWr    = (const float*)d_in[12];
    const float* in_gbr    = (const float*)d_in[13];
    const float* in_gV     = (const float*)d_in[14];
    const float* in_pWq    = (const float*)d_in[15];
    const float* in_pbq    = (const float*)d_in[16];
    const float* in_pWr    = (const float*)d_in[17];
    const float* in_pbr    = (const float*)d_in[18];
    const float* in_pV     = (const float*)d_in[19];
    const float* in_start  = (const float*)d_in[20];
    float* out = (float*)d_out;

    float* p_h0 = symaddr<float>(g_h0);
    float* p_h1 = symaddr<float>(g_h1);

    k_init<<<512, 256>>>();
    k_prep<<<4, 256>>>(in_emb, in_eWih, in_dWih, in_start);

    for (int t = 0; t < Sz; t++) {
        const float* rh = (t & 1) ? p_h1 : p_h0;
        float* wh       = (t & 1) ? p_h0 : p_h1;
        k_lstm_step<<<128, 512>>>(rh, wh, in_eWhh, in_ebih, in_ebhh, in_inputs, t, 0);
    }

    {
        dim3 grid(Hz / 64, (Bz * Sz) / 64, 2);
        k_ref<<<grid, 256>>>(in_gWr, in_gbr, in_pWr, in_pbr);
    }

    float* out_probs = out;
    float* out_idx = out + (size_t)Sz * Bz * Sz;
    for (int t = 0; t < Sz; t++) {
        const float* rh = (t & 1) ? p_h1 : p_h0;
        float* wh       = (t & 1) ? p_h0 : p_h1;
        k_lstm_step<<<128, 512>>>(rh, wh, in_dWhh, in_dbih, in_dbhh, in_inputs, t, 1);
        k_dec_attn<<<Bz / 4, 1024>>>(wh, in_gWq, in_gbq, in_gV, in_pWq, in_pbq, in_pV,
                                     out_probs + (size_t)t * Bz * Sz,
                                     out_idx + (size_t)t * Bz, t);
    }
    (void)in_sizes; (void)n_in; (void)out_size;
}

// round 12
// speedup vs baseline: 1.4726x; 1.1013x over previous
#include <cuda_runtime.h>
#include <cuda_bf16.h>
#include <math.h>
#include <stdint.h>

#define Bz 512
#define Sz 100
#define Ez 256
#define Hz 256
#define G4 1024
#define C_EXPLORE 10.0f
#define PARTITIONABLE 1

typedef unsigned long long u64;

// ---------------- packed f32x2 helpers (sm_100+) ----------------
__device__ __forceinline__ u64 pk2(float lo, float hi) {
    u64 d; asm("mov.b64 %0, {%1, %2};" : "=l"(d) : "f"(lo), "f"(hi)); return d;
}
__device__ __forceinline__ void upk2(u64 v, float& lo, float& hi) {
    asm("mov.b64 {%0, %1}, %2;" : "=f"(lo), "=f"(hi) : "l"(v));
}
__device__ __forceinline__ u64 fma2(u64 a, u64 b, u64 c) {
    u64 d; asm("fma.rn.f32x2 %0, %1, %2, %3;" : "=l"(d) : "l"(a), "l"(b), "l"(c)); return d;
}

// ---------------- fast exact-enough tanh (Eigen/XLA rational + rcp NR) ----------------
__device__ __forceinline__ float xtanh(float x) {
    const float c = 7.90531110763549805f;
    float cx = fminf(fmaxf(x, -c), c);
    float r = cx * cx;
    float p = -2.76076847742355e-16f;
    p = fmaf(p, r, 2.00018790482477e-13f);
    p = fmaf(p, r, -8.60467152213735e-11f);
    p = fmaf(p, r, 5.12229709037114e-08f);
    p = fmaf(p, r, 1.48572235717979e-05f);
    p = fmaf(p, r, 6.37261928875436e-04f);
    p = fmaf(p, r, 4.89352455891786e-03f);
    float num = cx * p;
    float q = 1.19825839466702e-06f;
    q = fmaf(q, r, 1.18534705686654e-04f);
    q = fmaf(q, r, 2.26843463243900e-03f);
    q = fmaf(q, r, 4.89352518554385e-03f);
    float ri;
    asm("rcp.approx.f32 %0, %1;" : "=f"(ri) : "f"(q));
    ri = ri * fmaf(-q, ri, 2.0f);
    return num * ri;
}
__device__ __forceinline__ float sigf(float x) {
    return 0.5f + 0.5f * xtanh(0.5f * x);
}

// ---------------- device state ----------------
__device__ float g_h0[Bz * Hz];
__device__ float g_c[Bz * Hz];
__device__ float g_enc[(size_t)Bz * Sz * Hz];
__device__ float g_refg[(size_t)Bz * Sz * Hz];
__device__ float g_refp[(size_t)Bz * Sz * Hz];
__device__ float g_Penc[2 * G4];
__device__ float g_Pdec[2 * G4];
__device__ float g_startproj[G4];
__device__ float4 g_WTe[64 * G4];   // [k4][row] : W[row][4k4..4k4+3]
__device__ float4 g_WTd[64 * G4];

// ---------------- threefry2x32 ----------------
__device__ __forceinline__ unsigned rotl32(unsigned v, int r) {
    return (v << r) | (v >> (32 - r));
}
__device__ __forceinline__ void tf2x32(unsigned k0, unsigned k1,
                                       unsigned x0, unsigned x1,
                                       unsigned& o0, unsigned& o1) {
    unsigned ks2 = 0x1BD11BDAu ^ k0 ^ k1;
    x0 += k0; x1 += k1;
#define TF_G(a,b,c,d) \
    x0 += x1; x1 = rotl32(x1,a); x1 ^= x0; \
    x0 += x1; x1 = rotl32(x1,b); x1 ^= x0; \
    x0 += x1; x1 = rotl32(x1,c); x1 ^= x0; \
    x0 += x1; x1 = rotl32(x1,d); x1 ^= x0;
    TF_G(13,15,26,6);  x0 += k1;  x1 += ks2 + 1u;
    TF_G(17,29,16,24); x0 += ks2; x1 += k0 + 2u;
    TF_G(13,15,26,6);  x0 += k0;  x1 += k1 + 3u;
    TF_G(17,29,16,24); x0 += k1;  x1 += ks2 + 4u;
    TF_G(13,15,26,6);  x0 += ks2; x1 += k0 + 5u;
#undef TF_G
    o0 = x0; o1 = x1;
}

// ---------------- setup ----------------
__global__ void k_prep(const float* __restrict__ emb,
                       const float* __restrict__ eWih,
                       const float* __restrict__ dWih,
                       const float* __restrict__ start) {
    int j = blockIdx.x * 256 + threadIdx.x;
    if (j >= G4) return;
    float pe0 = 0.f, pe1 = 0.f, pd0 = 0.f, pd1 = 0.f, sp = 0.f;
    for (int e = 0; e < Ez; e++) {
        float we = eWih[j * Ez + e], wd = dWih[j * Ez + e];
        pe0 = fmaf(emb[e], we, pe0);
        pe1 = fmaf(emb[Ez + e], we, pe1);
        pd0 = fmaf(emb[e], wd, pd0);
        pd1 = fmaf(emb[Ez + e], wd, pd1);
        sp  = fmaf(start[e], wd, sp);
    }
    g_Penc[j] = pe0; g_Penc[G4 + j] = pe1;
    g_Pdec[j] = pd0; g_Pdec[G4 + j] = pd1;
    g_startproj[j] = sp;
}

// transpose Whh -> k-major float4 tables (one-time)
__global__ void k_tr(const float* __restrict__ eWhh, const float* __restrict__ dWhh) {
    int idx = blockIdx.x * 256 + threadIdx.x;   // 0..65535
    const float* W = blockIdx.y ? dWhh : eWhh;
    float4* O = blockIdx.y ? g_WTd : g_WTe;
    int j = idx & (G4 - 1);
    int k4 = idx >> 10;
    O[idx] = *(const float4*)&W[(size_t)j * Hz + (k4 << 2)];
}

// ---------------- persistent encoder: 128 blocks x 1024 thr, 4 b per block ----------------
__global__ void __launch_bounds__(1024, 1) k_enc_p(const float* __restrict__ inp,
                                                   const float* __restrict__ bih,
                                                   const float* __restrict__ bhh) {
    __shared__ float hh[4][Hz];
    __shared__ float cc[4][Hz];
    __shared__ u64 hp[2][Hz];
    __shared__ float gat[4 * 4 * Hz];   // [g][b][jj]
    __shared__ float sbias[G4];
    __shared__ float P0[G4], P1[G4];

    const int tid = threadIdx.x;
    const int bb = blockIdx.x << 2;
    const int qt = tid >> 8, ht = tid & 255;

    hh[qt][ht] = 0.f;
    cc[qt][ht] = 0.f;
    sbias[tid] = bih[tid] + bhh[tid];
    P0[tid] = g_Penc[tid];
    P1[tid] = g_Penc[G4 + tid];
    __syncthreads();

    const float4* wt = g_WTe;
    for (int t = 0; t < Sz; t++) {
        // pack h pairs
        if (tid < 512) {
            int pr = tid >> 8, hx = tid & 255;
            hp[pr][hx] = pk2(hh[2 * pr][hx], hh[2 * pr + 1][hx]);
        }
        __syncthreads();
        // gates: thread = row (g*256+jj) = tid, accumulate 4 b's
        u64 a01 = pk2(0.f, 0.f), a23 = a01;
#pragma unroll 4
        for (int k4 = 0; k4 < 64; k4++) {
            float4 wv = wt[(k4 << 10) + tid];
            int k = k4 << 2;
            u64 w2;
            w2 = pk2(wv.x, wv.x); a01 = fma2(w2, hp[0][k], a01);     a23 = fma2(w2, hp[1][k], a23);
            w2 = pk2(wv.y, wv.y); a01 = fma2(w2, hp[0][k + 1], a01); a23 = fma2(w2, hp[1][k + 1], a23);
            w2 = pk2(wv.z, wv.z); a01 = fma2(w2, hp[0][k + 2], a01); a23 = fma2(w2, hp[1][k + 2], a23);
            w2 = pk2(wv.w, wv.w); a01 = fma2(w2, hp[0][k + 3], a01); a23 = fma2(w2, hp[1][k + 3], a23);
        }
        {
            float l0, l1, l2, l3;
            upk2(a01, l0, l1);
            upk2(a23, l2, l3);
            int gb = ((tid >> 8) << 10) + (tid & 255);
            gat[gb] = l0; gat[gb + 256] = l1; gat[gb + 512] = l2; gat[gb + 768] = l3;
        }
        __syncthreads();
        // cell: thread (b=qt, hidx=ht)
        {
            float a0 = gat[(qt << 8) + ht];
            float a1 = gat[1024 + (qt << 8) + ht];
            float a2 = gat[2048 + (qt << 8) + ht];
            float a3 = gat[3072 + (qt << 8) + ht];
            int b = bb + qt;
            float c0 = inp[(b * 2) * Sz + t];
            float c1 = inp[(b * 2 + 1) * Sz + t];
            float gi = a0 + fmaf(c0, P0[ht],        c1 * P1[ht])        + sbias[ht];
            float gf = a1 + fmaf(c0, P0[256 + ht],  c1 * P1[256 + ht])  + sbias[256 + ht];
            float gc = a2 + fmaf(c0, P0[512 + ht],  c1 * P1[512 + ht])  + sbias[512 + ht];
            float go = a3 + fmaf(c0, P0[768 + ht],  c1 * P1[768 + ht])  + sbias[768 + ht];
            float nc = sigf(gf) * cc[qt][ht] + sigf(gi) * xtanh(gc);
            cc[qt][ht] = nc;
            float nh = sigf(go) * xtanh(nc);
            hh[qt][ht] = nh;
            g_enc[((size_t)b * Sz + t) * Hz + ht] = nh;
        }
        __syncthreads();
    }
    // handoff to decoder
    {
        int b = bb + qt;
        g_h0[(b << 8) + ht] = hh[qt][ht];
        g_c[(b << 8) + ht] = cc[qt][ht];
    }
}

// ---------------- ref projections (z=0: glimpse, z=1: pointer) ----------------
__global__ void __launch_bounds__(256) k_ref(const float* __restrict__ gWr,
                                             const float* __restrict__ gbr,
                                             const float* __restrict__ pWr,
                                             const float* __restrict__ pbr) {
    __shared__ float As[16][64];
    __shared__ float Ws[16][64];
    const float* A = g_enc;
    const float* W = blockIdx.z ? pWr : gWr;
    const float* bias = blockIdx.z ? pbr : gbr;
    float* C = blockIdx.z ? g_refp : g_refg;
    const int K = Hz, N = Hz;
    const int bm = blockIdx.y * 64;
    const int bn = blockIdx.x * 64;
    const int t = threadIdx.x;
    const int tx = t & 15, ty = t >> 4;
    const int lr = t >> 2, lc = (t & 3) << 2;
    float acc[4][4];
#pragma unroll
    for (int i = 0; i < 4; i++)
#pragma unroll
        for (int jj = 0; jj < 4; jj++) acc[i][jj] = 0.f;
    const float* Ab = A + (size_t)(bm + lr) * K + lc;
    const float* Wb = W + (size_t)(bn + lr) * K + lc;
    for (int k0 = 0; k0 < K; k0 += 16) {
        float4 av = *(const float4*)(Ab + k0);
        float4 wv = *(const float4*)(Wb + k0);
        As[lc + 0][lr] = av.x; As[lc + 1][lr] = av.y;
        As[lc + 2][lr] = av.z; As[lc + 3][lr] = av.w;
        Ws[lc + 0][lr] = wv.x; Ws[lc + 1][lr] = wv.y;
        Ws[lc + 2][lr] = wv.z; Ws[lc + 3][lr] = wv.w;
        __syncthreads();
#pragma unroll
        for (int k = 0; k < 16; k++) {
            float4 a4 = *(const float4*)&As[k][ty << 2];
            float4 w4 = *(const float4*)&Ws[k][tx << 2];
            float am[4] = {a4.x, a4.y, a4.z, a4.w};
            float wn[4] = {w4.x, w4.y, w4.z, w4.w};
#pragma unroll
            for (int i = 0; i < 4; i++)
#pragma unroll
                for (int jj = 0; jj < 4; jj++)
                    acc[i][jj] = fmaf(am[i], wn[jj], acc[i][jj]);
        }
        __syncthreads();
    }
#pragma unroll
    for (int i = 0; i < 4; i++) {
        int m = bm + (ty << 2) + i;
#pragma unroll
        for (int jj = 0; jj < 4; jj++) {
            int n = bn + (tx << 2) + jj;
            C[(size_t)m * N + n] = acc[i][jj] + bias[n];
        }
    }
}

// warp 4-way reduce
__device__ __forceinline__ void wredd4(float& a0, float& a1, float& a2, float& a3) {
#pragma unroll
    for (int o = 16; o; o >>= 1) {
        a0 += __shfl_xor_sync(0xffffffffu, a0, o);
        a1 += __shfl_xor_sync(0xffffffffu, a1, o);
        a2 += __shfl_xor_sync(0xffffffffu, a2, o);
        a3 += __shfl_xor_sync(0xffffffffu, a3, o);
    }
}

// ---------------- persistent decoder smem layout ----------------
struct __align__(16) SmemDec {
    float hh[4][Hz];
    float cc[4][Hz];
    u64 hp[2][Hz];
    float gat[4 * 4 * Hz];
    float sbias[G4];
    float P0[G4], P1[G4];
    float qq[4][Hz];
    float qv[4][Hz];
    float Vg[Hz], Vp[Hz];
    float lg[4][128];
    float w[4][128];
    float red[4][256];
    int ridx[4][256];
    short list[4][104];
    unsigned char m[4][104];
    int ccnt[4][4];
    int idx[4];
};

// ---------------- persistent decoder: 128 blocks x 1024 thr, 4 b/block, 100 steps ----------------
__global__ void __launch_bounds__(1024, 1) k_dec_p(const float* __restrict__ inp,
                                                   const float* __restrict__ dbih,
                                                   const float* __restrict__ dbhh,
                                                   const float* __restrict__ gWq,
                                                   const float* __restrict__ gbq,
                                                   const float* __restrict__ gV,
                                                   const float* __restrict__ pWq,
                                                   const float* __restrict__ pbq,
                                                   const float* __restrict__ pV,
                                                   float* __restrict__ out) {
    extern __shared__ char smraw[];
    SmemDec* sm = (SmemDec*)smraw;

    const int tid = threadIdx.x;
    const int bb = blockIdx.x << 2;
    const int qt = tid >> 8, ht = tid & 255;
    const int wd = tid >> 5, ln = tid & 31;
    const int b = bb + qt;

    sm->hh[qt][ht] = g_h0[(b << 8) + ht];
    sm->cc[qt][ht] = g_c[(b << 8) + ht];
    sm->sbias[tid] = dbih[tid] + dbhh[tid];
    sm->P0[tid] = g_Pdec[tid];
    sm->P1[tid] = g_Pdec[G4 + tid];
    if (tid < Hz) sm->Vg[tid] = gV[tid];
    else if (tid < 2 * Hz) sm->Vp[tid - Hz] = pV[tid - Hz];
    if (ht < Sz) sm->m[qt][ht] = 0;
    if (tid < 4) sm->idx[tid] = 0;
    __syncthreads();

    float* out_probs = out;
    float* out_idx = out + (size_t)Sz * Bz * Sz;
    const float4* wt = g_WTd;

    for (int t = 0; t < Sz; t++) {
        // ---- pack h pairs ----
        if (tid < 512) {
            int pr = tid >> 8, hx = tid & 255;
            sm->hp[pr][hx] = pk2(sm->hh[2 * pr][hx], sm->hh[2 * pr + 1][hx]);
        }
        __syncthreads();
        // ---- gates matvec (bit-identical k-order) ----
        u64 a01 = pk2(0.f, 0.f), a23 = a01;
#pragma unroll 4
        for (int k4 = 0; k4 < 64; k4++) {
            float4 wv = wt[(k4 << 10) + tid];
            int k = k4 << 2;
            u64 w2;
            w2 = pk2(wv.x, wv.x); a01 = fma2(w2, sm->hp[0][k], a01);     a23 = fma2(w2, sm->hp[1][k], a23);
            w2 = pk2(wv.y, wv.y); a01 = fma2(w2, sm->hp[0][k + 1], a01); a23 = fma2(w2, sm->hp[1][k + 1], a23);
            w2 = pk2(wv.z, wv.z); a01 = fma2(w2, sm->hp[0][k + 2], a01); a23 = fma2(w2, sm->hp[1][k + 2], a23);
            w2 = pk2(wv.w, wv.w); a01 = fma2(w2, sm->hp[0][k + 3], a01); a23 = fma2(w2, sm->hp[1][k + 3], a23);
        }
        {
            float l0, l1, l2, l3;
            upk2(a01, l0, l1);
            upk2(a23, l2, l3);
            int gb = ((tid >> 8) << 10) + (tid & 255);
            sm->gat[gb] = l0; sm->gat[gb + 256] = l1; sm->gat[gb + 512] = l2; sm->gat[gb + 768] = l3;
        }
        __syncthreads();
        // ---- LSTM cell (thread = (b=qt, hidx=ht)) ----
        {
            float a0 = sm->gat[(qt << 8) + ht];
            float a1 = sm->gat[1024 + (qt << 8) + ht];
            float a2 = sm->gat[2048 + (qt << 8) + ht];
            float a3 = sm->gat[3072 + (qt << 8) + ht];
            float xg0, xg1, xg2, xg3;
            if (t == 0) {
                xg0 = g_startproj[ht];
                xg1 = g_startproj[256 + ht];
                xg2 = g_startproj[512 + ht];
                xg3 = g_startproj[768 + ht];
            } else {
                int s = sm->idx[qt];
                float c0 = inp[(b * 2) * Sz + s];
                float c1 = inp[(b * 2 + 1) * Sz + s];
                xg0 = fmaf(c0, sm->P0[ht],       c1 * sm->P1[ht]);
                xg1 = fmaf(c0, sm->P0[256 + ht], c1 * sm->P1[256 + ht]);
                xg2 = fmaf(c0, sm->P0[512 + ht], c1 * sm->P1[512 + ht]);
                xg3 = fmaf(c0, sm->P0[768 + ht], c1 * sm->P1[768 + ht]);
            }
            float gi = a0 + xg0 + sm->sbias[ht];
            float gf = a1 + xg1 + sm->sbias[256 + ht];
            float gc = a2 + xg2 + sm->sbias[512 + ht];
            float go = a3 + xg3 + sm->sbias[768 + ht];
            float nc = sigf(gf) * sm->cc[qt][ht] + sigf(gi) * xtanh(gc);
            sm->cc[qt][ht] = nc;
            sm->hh[qt][ht] = sigf(go) * xtanh(nc);
        }
        __syncthreads();

        // ==================== attention + sample (per-b local) ====================
        if (t > 0 && ht == 0) sm->m[qt][sm->idx[qt]] = 1;
        __syncthreads();

        // deterministic compaction of unmasked s (ascending, per quarter)
        bool un = false; int pre = 0, chunk = 0;
        if (ht < 128) {
            chunk = ht >> 5;
            un = (ht < Sz) && !sm->m[qt][ht];
            unsigned bal = __ballot_sync(0xffffffffu, un);
            pre = __popc(bal & ((1u << (ht & 31)) - 1));
            if ((ht & 31) == 0) sm->ccnt[qt][chunk] = __popc(bal);
        }
        __syncthreads();
        int nq[4];
#pragma unroll
        for (int g = 0; g < 4; g++)
            nq[g] = sm->ccnt[g][0] + sm->ccnt[g][1] + sm->ccnt[g][2] + sm->ccnt[g][3];
        const int n_self = nq[qt];
        int nmax = nq[0];
#pragma unroll
        for (int g = 1; g < 4; g++) nmax = nq[g] > nmax ? nq[g] : nmax;
        if (un) {
            int base = 0;
            for (int i = 0; i < chunk; i++) base += sm->ccnt[qt][i];
            sm->list[qt][base + pre] = (short)ht;
        }
        if (ht < 128) sm->lg[qt][ht] = -INFINITY;
        __syncthreads();

        // qq = h @ gWq^T + gbq, warp-cooperative rows for all 4 b's
        for (int row = wd; row < Hz; row += 32) {
            const float4* wr = (const float4*)(gWq + (size_t)row * Hz);
            float4 w1 = wr[ln], w2 = wr[32 + ln];
            float a[4];
#pragma unroll
            for (int g = 0; g < 4; g++) {
                float4 ha = *(const float4*)&sm->hh[g][ln << 2];
                float4 hb = *(const float4*)&sm->hh[g][128 + (ln << 2)];
                float ag = 0.f;
                ag = fmaf(w1.x, ha.x, ag); ag = fmaf(w1.y, ha.y, ag);
                ag = fmaf(w1.z, ha.z, ag); ag = fmaf(w1.w, ha.w, ag);
                ag = fmaf(w2.x, hb.x, ag); ag = fmaf(w2.y, hb.y, ag);
                ag = fmaf(w2.z, hb.z, ag); ag = fmaf(w2.w, hb.w, ag);
                a[g] = ag;
            }
            wredd4(a[0], a[1], a[2], a[3]);
            if (!ln) {
                float bq = gbq[row];
#pragma unroll
                for (int g = 0; g < 4; g++) sm->qq[g][row] = a[g] + bq;
            }
        }
        __syncthreads();
        // glimpse logits over compact lists
        for (int ii = wd; ii < nmax; ii += 32) {
            int sg[4]; float a[4];
#pragma unroll
            for (int g = 0; g < 4; g++) {
                sg[g] = (ii < nq[g]) ? sm->list[g][ii] : -1;
                a[g] = 0.f;
            }
#pragma unroll
            for (int g = 0; g < 4; g++) {
                if (sg[g] >= 0) {
                    const float4* rg = (const float4*)(g_refg + ((size_t)(bb + g) * Sz + sg[g]) * Hz);
#pragma unroll
                    for (int i = 0; i < 2; i++) {
                        int c = i * 32 + ln;
                        float4 rv = rg[c];
                        float4 qvv = *(const float4*)&sm->qq[g][c << 2];
                        float4 vv = *(const float4*)&sm->Vg[c << 2];
                        a[g] = fmaf(vv.x, xtanh(qvv.x + rv.x), a[g]);
                        a[g] = fmaf(vv.y, xtanh(qvv.y + rv.y), a[g]);
                        a[g] = fmaf(vv.z, xtanh(qvv.z + rv.z), a[g]);
                        a[g] = fmaf(vv.w, xtanh(qvv.w + rv.w), a[g]);
                    }
                }
            }
            wredd4(a[0], a[1], a[2], a[3]);
            if (!ln) {
#pragma unroll
                for (int g = 0; g < 4; g++)
                    if (sg[g] >= 0) sm->lg[g][sg[g]] = a[g];
            }
        }
        __syncthreads();
        // softmax -> w (per quarter)
        {
            float v = (ht < Sz) ? sm->lg[qt][ht] : -INFINITY;
            sm->red[qt][ht] = v; __syncthreads();
#pragma unroll
            for (int o = 128; o; o >>= 1) { if (ht < o) sm->red[qt][ht] = fmaxf(sm->red[qt][ht], sm->red[qt][ht + o]); __syncthreads(); }
            float m = sm->red[qt][0]; __syncthreads();
            float e = (ht < Sz) ? expf(v - m) : 0.f;
            sm->red[qt][ht] = e; __syncthreads();
#pragma unroll
            for (int o = 128; o; o >>= 1) { if (ht < o) sm->red[qt][ht] += sm->red[qt][ht + o]; __syncthreads(); }
            float smv = sm->red[qt][0]; __syncthreads();
            if (ht < 128) sm->w[qt][ht] = (ht < Sz) ? e / smv : 0.f;
        }
        __syncthreads();
        // q = sum over unmasked s of w[s]*enc[b,s,:]
        {
            float av[8];
#pragma unroll
            for (int i = 0; i < 8; i++) av[i] = 0.f;
            const float* eb = g_enc + (size_t)b * Sz * Hz + ht;
            int ii = 0;
            for (; ii + 8 <= n_self; ii += 8) {
#pragma unroll
                for (int i = 0; i < 8; i++) {
                    int s = sm->list[qt][ii + i];
                    av[i] = fmaf(sm->w[qt][s], eb[(size_t)s * Hz], av[i]);
                }
            }
            for (; ii < n_self; ii++) {
                int s = sm->list[qt][ii];
                av[ii & 7] = fmaf(sm->w[qt][s], eb[(size_t)s * Hz], av[ii & 7]);
            }
            sm->qv[qt][ht] = ((av[0] + av[1]) + (av[2] + av[3])) + ((av[4] + av[5]) + (av[6] + av[7]));
        }
        __syncthreads();
        // qq2 = q @ pWq^T + pbq
        for (int row = wd; row < Hz; row += 32) {
            const float4* wr = (const float4*)(pWq + (size_t)row * Hz);
            float4 w1 = wr[ln], w2 = wr[32 + ln];
            float a[4];
#pragma unroll
            for (int g = 0; g < 4; g++) {
                float4 ha = *(const float4*)&sm->qv[g][ln << 2];
                float4 hb = *(const float4*)&sm->qv[g][128 + (ln << 2)];
                float ag = 0.f;
                ag = fmaf(w1.x, ha.x, ag); ag = fmaf(w1.y, ha.y, ag);
                ag = fmaf(w1.z, ha.z, ag); ag = fmaf(w1.w, ha.w, ag);
                ag = fmaf(w2.x, hb.x, ag); ag = fmaf(w2.y, hb.y, ag);
                ag = fmaf(w2.z, hb.z, ag); ag = fmaf(w2.w, hb.w, ag);
                a[g] = ag;
            }
            wredd4(a[0], a[1], a[2], a[3]);
            if (!ln) {
                float bq = pbq[row];
#pragma unroll
                for (int g = 0; g < 4; g++) sm->qq[g][row] = a[g] + bq;
            }
        }
        __syncthreads();
        // pointer logits over compact lists
        for (int ii = wd; ii < nmax; ii += 32) {
            int sg[4]; float a[4];
#pragma unroll
            for (int g = 0; g < 4; g++) {
                sg[g] = (ii < nq[g]) ? sm->list[g][ii] : -1;
                a[g] = 0.f;
            }
#pragma unroll
            for (int g = 0; g < 4; g++) {
                if (sg[g] >= 0) {
                    const float4* rp = (const float4*)(g_refp + ((size_t)(bb + g) * Sz + sg[g]) * Hz);
#pragma unroll
                    for (int i = 0; i < 2; i++) {
                        int c = i * 32 + ln;
                        float4 rv = rp[c];
                        float4 qvv = *(const float4*)&sm->qq[g][c << 2];
                        float4 vv = *(const float4*)&sm->Vp[c << 2];
                        a[g] = fmaf(vv.x, xtanh(qvv.x + rv.x), a[g]);
                        a[g] = fmaf(vv.y, xtanh(qvv.y + rv.y), a[g]);
                        a[g] = fmaf(vv.z, xtanh(qvv.z + rv.z), a[g]);
                        a[g] = fmaf(vv.w, xtanh(qvv.w + rv.w), a[g]);
                    }
                }
            }
            wredd4(a[0], a[1], a[2], a[3]);
            if (!ln) {
#pragma unroll
                for (int g = 0; g < 4; g++)
                    if (sg[g] >= 0) sm->lg[g][sg[g]] = C_EXPLORE * xtanh(a[g]);
            }
        }
        __syncthreads();
        // softmax -> probs; gumbel argmax -> idx
        {
            float v = (ht < Sz) ? sm->lg[qt][ht] : -INFINITY;
            sm->red[qt][ht] = v; __syncthreads();
#pragma unroll
            for (int o = 128; o; o >>= 1) { if (ht < o) sm->red[qt][ht] = fmaxf(sm->red[qt][ht], sm->red[qt][ht + o]); __syncthreads(); }
            float m = sm->red[qt][0]; __syncthreads();
            float e = (ht < Sz) ? expf(v - m) : 0.f;
            sm->red[qt][ht] = e; __syncthreads();
#pragma unroll
            for (int o = 128; o; o >>= 1) { if (ht < o) sm->red[qt][ht] += sm->red[qt][ht + o]; __syncthreads(); }
            float smv = sm->red[qt][0]; __syncthreads();
            if (ht < Sz)
                out_probs[(size_t)t * Bz * Sz + (size_t)b * Sz + ht] = e / smv;
            float pv = -INFINITY;
            if (ht < Sz) {
                unsigned key0, key1;
#if PARTITIONABLE
                tf2x32(0u, 1u, 0u, (unsigned)t, key0, key1);
#else
                {
                    unsigned a0k, b0k;
                    unsigned idx0 = 2u * t, idx1 = 2u * t + 1u;
                    if (idx0 < Sz) { tf2x32(0u, 1u, idx0, idx0 + Sz, a0k, b0k); key0 = a0k; }
                    else           { tf2x32(0u, 1u, idx0 - Sz, idx0, a0k, b0k); key0 = b0k; }
                    if (idx1 < Sz) { tf2x32(0u, 1u, idx1, idx1 + Sz, a0k, b0k); key1 = a0k; }
                    else           { tf2x32(0u, 1u, idx1 - Sz, idx1, a0k, b0k); key1 = b0k; }
                }
#endif
                unsigned m0 = (unsigned)(b * Sz + ht);
                unsigned ra, rb, bits;
#if PARTITIONABLE
                tf2x32(key0, key1, 0u, m0, ra, rb);
                bits = ra ^ rb;
#else
                const unsigned halfn = (Bz * Sz) / 2;
                if (m0 < halfn) { tf2x32(key0, key1, m0, m0 + halfn, ra, rb); bits = ra; }
                else            { tf2x32(key0, key1, m0 - halfn, m0, ra, rb); bits = rb; }
#endif
                float f = __uint_as_float((bits >> 9) | 0x3f800000u) - 1.0f;
                float u = fmaxf(f, 1.17549435e-38f);
                pv = v - logf(-logf(u));
            }
            sm->red[qt][ht] = pv; sm->ridx[qt][ht] = ht; __syncthreads();
#pragma unroll
            for (int o = 128; o; o >>= 1) {
                if (ht < o) {
                    float a2 = sm->red[qt][ht], c2 = sm->red[qt][ht + o];
                    int ia = sm->ridx[qt][ht], ic = sm->ridx[qt][ht + o];
                    if (c2 > a2 || (c2 == a2 && ic < ia)) { sm->red[qt][ht] = c2; sm->ridx[qt][ht] = ic; }
                }
                __syncthreads();
            }
            if (!ht) {
                int id = sm->ridx[qt][0];
                sm->idx[qt] = id;
                out_idx[(size_t)t * Bz + b] = (float)id;
            }
        }
        __syncthreads();
    }
}

// ---------------- host ----------------
extern "C" void kernel_launch(void* const* d_in, const int* in_sizes, int n_in,
                              void* d_out, int out_size) {
    const float* in_inputs = (const float*)d_in[0];
    const float* in_emb    = (const float*)d_in[1];
    const float* in_eWih   = (const float*)d_in[2];
    const float* in_eWhh   = (const float*)d_in[3];
    const float* in_ebih   = (const float*)d_in[4];
    const float* in_ebhh   = (const float*)d_in[5];
    const float* in_dWih   = (const float*)d_in[6];
    const float* in_dWhh   = (const float*)d_in[7];
    const float* in_dbih   = (const float*)d_in[8];
    const float* in_dbhh   = (const float*)d_in[9];
    const float* in_gWq    = (const float*)d_in[10];
    const float* in_gbq    = (const float*)d_in[11];
    const float* in_gWr    = (const float*)d_in[12];
    const float* in_gbr    = (const float*)d_in[13];
    const float* in_gV     = (const float*)d_in[14];
    const float* in_pWq    = (const float*)d_in[15];
    const float* in_pbq    = (const float*)d_in[16];
    const float* in_pWr    = (const float*)d_in[17];
    const float* in_pbr    = (const float*)d_in[18];
    const float* in_pV     = (const float*)d_in[19];
    const float* in_start  = (const float*)d_in[20];
    float* out = (float*)d_out;

    static bool attr_set = false;
    if (!attr_set) {
        cudaFuncSetAttribute(k_dec_p, cudaFuncAttributeMaxDynamicSharedMemorySize,
                             (int)sizeof(SmemDec));
        attr_set = true;
    }

    k_prep<<<4, 256>>>(in_emb, in_eWih, in_dWih, in_start);
    {
        dim3 grid(256, 2);
        k_tr<<<grid, 256>>>(in_eWhh, in_dWhh);
    }
    k_enc_p<<<128, 1024>>>(in_inputs, in_ebih, in_ebhh);
    {
        dim3 grid(Hz / 64, (Bz * Sz) / 64, 2);
        k_ref<<<grid, 256>>>(in_gWr, in_gbr, in_pWr, in_pbr);
    }
    k_dec_p<<<128, 1024, sizeof(SmemDec)>>>(in_inputs, in_dbih, in_dbhh,
                                            in_gWq, in_gbq, in_gV,
                                            in_pWq, in_pbq, in_pV, out);
    (void)in_sizes; (void)n_in; (void)out_size;
}